// round 2
// baseline (speedup 1.0000x reference)
#include <cuda_runtime.h>
#include <cuda_bf16.h>
#include <math.h>
#include <float.h>

// Problem constants
#define T_LEN   4096
#define C_DIM   2048
#define HQ      16
#define HKV     4
#define HD      128
#define WIN     1024

// Scratch (device globals; no allocations allowed)
__device__ float g_Q[T_LEN * HQ * HD];     // 4096 x 2048
__device__ float g_K[T_LEN * HKV * HD];    // 4096 x 512
__device__ float g_V[T_LEN * HKV * HD];    // 4096 x 512
__device__ float g_Y[T_LEN * HQ * HD];     // 4096 x 2048
__device__ float g_cos[T_LEN * 64];
__device__ float g_sin[T_LEN * 64];

// ---------------------------------------------------------------------------
// SGEMM: C[M,N] = A[M,K] * B[K,N], all row-major, fp32.
// 128x128 block tile, BK=16, 256 threads, 8x8 per-thread micro-tile.
// ---------------------------------------------------------------------------
__global__ __launch_bounds__(256, 2)
void sgemm128(const float* __restrict__ A, const float* __restrict__ B,
              float* __restrict__ C, int M, int N, int Kd)
{
    __shared__ float As[16][128];
    __shared__ float Bs[16][128];

    const int tid = threadIdx.x;
    const int bx = blockIdx.x, by = blockIdx.y;
    const int ty = tid >> 4;        // 0..15
    const int tx = tid & 15;        // 0..15

    const int a_m = tid >> 2;           // 0..63
    const int a_k = (tid & 3) << 2;     // 0,4,8,12
    const int b_k = tid >> 5;           // 0..7
    const int b_n = (tid & 31) << 2;    // 0..124

    const float* Aptr = A + (size_t)(by * 128) * Kd;
    const float* Bptr = B + bx * 128;

    float acc[8][8];
#pragma unroll
    for (int i = 0; i < 8; i++)
#pragma unroll
        for (int j = 0; j < 8; j++) acc[i][j] = 0.0f;

    for (int k0 = 0; k0 < Kd; k0 += 16) {
#pragma unroll
        for (int rr = 0; rr < 2; rr++) {
            float4 av = *(const float4*)(Aptr + (size_t)(a_m + 64 * rr) * Kd + k0 + a_k);
            As[a_k + 0][a_m + 64 * rr] = av.x;
            As[a_k + 1][a_m + 64 * rr] = av.y;
            As[a_k + 2][a_m + 64 * rr] = av.z;
            As[a_k + 3][a_m + 64 * rr] = av.w;
            float4 bv = *(const float4*)(Bptr + (size_t)(k0 + b_k + 8 * rr) * N + b_n);
            *(float4*)&Bs[b_k + 8 * rr][b_n] = bv;
        }
        __syncthreads();

#pragma unroll
        for (int kk = 0; kk < 16; kk++) {
            float ra[8], rb[8];
            *(float4*)&ra[0] = *(const float4*)&As[kk][ty * 8];
            *(float4*)&ra[4] = *(const float4*)&As[kk][ty * 8 + 4];
            *(float4*)&rb[0] = *(const float4*)&Bs[kk][tx * 8];
            *(float4*)&rb[4] = *(const float4*)&Bs[kk][tx * 8 + 4];
#pragma unroll
            for (int i = 0; i < 8; i++)
#pragma unroll
                for (int j = 0; j < 8; j++)
                    acc[i][j] += ra[i] * rb[j];
        }
        __syncthreads();
    }

#pragma unroll
    for (int i = 0; i < 8; i++) {
        float* cp = C + (size_t)(by * 128 + ty * 8 + i) * N + bx * 128 + tx * 8;
        float4 w0 = make_float4(acc[i][0], acc[i][1], acc[i][2], acc[i][3]);
        float4 w1 = make_float4(acc[i][4], acc[i][5], acc[i][6], acc[i][7]);
        *(float4*)cp = w0;
        *(float4*)(cp + 4) = w1;
    }
}

// ---------------------------------------------------------------------------
// RoPE cos/sin table (fp32 angle rounding like reference; fp64 trig).
// ---------------------------------------------------------------------------
__global__ void rope_table_kernel()
{
    int idx = blockIdx.x * blockDim.x + threadIdx.x;
    if (idx >= T_LEN * 64) return;
    int t = idx >> 6;
    int j = idx & 63;
    double e = exp(-(double)j * (log(10000.0) / 64.0));
    float invf = (float)e;
    float ang = (float)t * invf;
    double a = (double)ang;
    g_cos[idx] = (float)cos(a);
    g_sin[idx] = (float)sin(a);
}

// Apply RoPE in-place to Q [T, HQ*HD] and K [T, HKV*HD].
__global__ void rope_apply_kernel(float* __restrict__ Q, float* __restrict__ K)
{
    const int NQ = T_LEN * HQ * 64;
    int idx = blockIdx.x * blockDim.x + threadIdx.x;
    float* p;
    int t, j;
    if (idx < NQ) {
        t = idx >> 10;
        int rem = idx & 1023;
        int h = rem >> 6;
        j = rem & 63;
        p = Q + (size_t)t * (HQ * HD) + h * HD;
    } else {
        int i2 = idx - NQ;
        t = i2 >> 8;
        int rem = i2 & 255;
        int h = rem >> 6;
        j = rem & 63;
        p = K + (size_t)t * (HKV * HD) + h * HD;
    }
    float cv = g_cos[t * 64 + j];
    float sv = g_sin[t * 64 + j];
    float x0 = p[j];
    float x1 = p[j + 64];
    p[j]      = x0 * cv - x1 * sv;
    p[j + 64] = x1 * cv + x0 * sv;
}

// ---------------------------------------------------------------------------
// Sliding-window causal attention, fp32, BRANCHLESS online softmax
// (divergent shuffle in round 1 deadlocked at the left window edge).
// Grid: (T/16, HQ). Block: 128 threads. Tile: 16 q x 32 k.
// ---------------------------------------------------------------------------
__global__ __launch_bounds__(128)
void attn_kernel(const float* __restrict__ Q, const float* __restrict__ K,
                 const float* __restrict__ V, float* __restrict__ Y)
{
    const int BQ = 16, BK = 32;
    __shared__ float Qs[BQ][HD];
    __shared__ float Ks[BK][HD];
    __shared__ float Vs[BK][HD];
    __shared__ float Ps[BQ][BK];

    const int qb = blockIdx.x;
    const int h  = blockIdx.y;
    const int kvh = h >> 2;

    const int tid = threadIdx.x;
    const int r = tid >> 3;
    const int c = tid & 7;
    const int d0 = c * 16;

    const int q_i = qb * BQ + r;

#pragma unroll
    for (int it = 0; it < 4; it++) {
        int idx4 = tid + 128 * it;
        int row = idx4 >> 5;
        int dd4 = idx4 & 31;
        int t = qb * BQ + row;
        float4 qv = *(const float4*)(Q + (size_t)t * (HQ * HD) + h * HD + dd4 * 4);
        *(float4*)&Qs[row][dd4 * 4] = qv;
    }

    float o[16];
#pragma unroll
    for (int i = 0; i < 16; i++) o[i] = 0.0f;
    float m = -INFINITY;
    float l = 0.0f;

    int j_min = qb * BQ - (WIN - 1);
    if (j_min < 0) j_min = 0;
    const int kb0 = j_min / BK;
    const int kb1 = (qb * BQ + BQ - 1) / BK;

    const float sc = 0.08838834764831845f;

    for (int kb = kb0; kb <= kb1; kb++) {
        const int jbase = kb * BK;
#pragma unroll
        for (int it = 0; it < 8; it++) {
            int idx4 = tid + 128 * it;
            int row = idx4 >> 5;
            int dd4 = idx4 & 31;
            size_t goff = (size_t)(jbase + row) * (HKV * HD) + kvh * HD + dd4 * 4;
            *(float4*)&Ks[row][dd4 * 4] = *(const float4*)(K + goff);
            *(float4*)&Vs[row][dd4 * 4] = *(const float4*)(V + goff);
        }
        __syncthreads();

        float s0 = 0.f, s1 = 0.f, s2 = 0.f, s3 = 0.f;
#pragma unroll
        for (int d4 = 0; d4 < 32; d4++) {
            float4 q  = *(const float4*)&Qs[r][d4 * 4];
            float4 k0 = *(const float4*)&Ks[c][d4 * 4];
            float4 k1 = *(const float4*)&Ks[c + 8][d4 * 4];
            float4 k2 = *(const float4*)&Ks[c + 16][d4 * 4];
            float4 k3 = *(const float4*)&Ks[c + 24][d4 * 4];
            s0 += q.x * k0.x + q.y * k0.y + q.z * k0.z + q.w * k0.w;
            s1 += q.x * k1.x + q.y * k1.y + q.z * k1.z + q.w * k1.w;
            s2 += q.x * k2.x + q.y * k2.y + q.z * k2.z + q.w * k2.w;
            s3 += q.x * k3.x + q.y * k3.y + q.z * k3.z + q.w * k3.w;
        }

        float sv[4] = { s0 * sc, s1 * sc, s2 * sc, s3 * sc };
#pragma unroll
        for (int u = 0; u < 4; u++) {
            int j = jbase + c + 8 * u;
            bool ok = (j <= q_i) && ((q_i - j) < WIN);
            if (!ok) sv[u] = -INFINITY;
        }

        float bm = fmaxf(fmaxf(sv[0], sv[1]), fmaxf(sv[2], sv[3]));
#pragma unroll
        for (int off = 4; off >= 1; off >>= 1)
            bm = fmaxf(bm, __shfl_xor_sync(0xffffffffu, bm, off));

        float m_new = fmaxf(m, bm);
        float mm = (m_new == -INFINITY) ? 0.0f : m_new;
        float factor = expf(m - mm);
        float p0 = expf(sv[0] - mm);
        float p1 = expf(sv[1] - mm);
        float p2 = expf(sv[2] - mm);
        float p3 = expf(sv[3] - mm);
        float psum = p0 + p1 + p2 + p3;
#pragma unroll
        for (int off = 4; off >= 1; off >>= 1)
            psum += __shfl_xor_sync(0xffffffffu, psum, off);
        l = l * factor + psum;
        m = m_new;
#pragma unroll
        for (int i = 0; i < 16; i++) o[i] *= factor;
        Ps[r][c]      = p0;
        Ps[r][c + 8]  = p1;
        Ps[r][c + 16] = p2;
        Ps[r][c + 24] = p3;
        __syncthreads();

#pragma unroll
        for (int k = 0; k < BK; k++) {
            float p = Ps[r][k];
            float4 v0 = *(const float4*)&Vs[k][d0];
            float4 v1 = *(const float4*)&Vs[k][d0 + 4];
            float4 v2 = *(const float4*)&Vs[k][d0 + 8];
            float4 v3 = *(const float4*)&Vs[k][d0 + 12];
            o[0]  += p * v0.x; o[1]  += p * v0.y; o[2]  += p * v0.z; o[3]  += p * v0.w;
            o[4]  += p * v1.x; o[5]  += p * v1.y; o[6]  += p * v1.z; o[7]  += p * v1.w;
            o[8]  += p * v2.x; o[9]  += p * v2.y; o[10] += p * v2.z; o[11] += p * v2.w;
            o[12] += p * v3.x; o[13] += p * v3.y; o[14] += p * v3.z; o[15] += p * v3.w;
        }
        __syncthreads();
    }

    float inv_l = 1.0f / l;
    float* yp = Y + (size_t)q_i * (HQ * HD) + h * HD + d0;
#pragma unroll
    for (int i4 = 0; i4 < 4; i4++) {
        float4 w = make_float4(o[i4 * 4 + 0] * inv_l, o[i4 * 4 + 1] * inv_l,
                               o[i4 * 4 + 2] * inv_l, o[i4 * 4 + 3] * inv_l);
        *(float4*)(yp + i4 * 4) = w;
    }
}

// ---------------------------------------------------------------------------
// Launch
// ---------------------------------------------------------------------------
extern "C" void kernel_launch(void* const* d_in, const int* in_sizes, int n_in,
                              void* d_out, int out_size)
{
    const float* x  = (const float*)d_in[0];
    const float* Wq = (const float*)d_in[1];
    const float* Wk = (const float*)d_in[2];
    const float* Wv = (const float*)d_in[3];
    const float* Wo = (const float*)d_in[4];
    float* out = (float*)d_out;

    float *Q, *Kp, *Vp, *Yp;
    cudaGetSymbolAddress((void**)&Q,  g_Q);
    cudaGetSymbolAddress((void**)&Kp, g_K);
    cudaGetSymbolAddress((void**)&Vp, g_V);
    cudaGetSymbolAddress((void**)&Yp, g_Y);

    sgemm128<<<dim3(C_DIM / 128, T_LEN / 128), 256>>>(x, Wq, Q,  T_LEN, HQ * HD,  C_DIM);
    sgemm128<<<dim3((HKV * HD) / 128, T_LEN / 128), 256>>>(x, Wk, Kp, T_LEN, HKV * HD, C_DIM);
    sgemm128<<<dim3((HKV * HD) / 128, T_LEN / 128), 256>>>(x, Wv, Vp, T_LEN, HKV * HD, C_DIM);

    rope_table_kernel<<<(T_LEN * 64 + 255) / 256, 256>>>();
    const int n_rope = T_LEN * HQ * 64 + T_LEN * HKV * 64;
    rope_apply_kernel<<<n_rope / 256, 256>>>(Q, Kp);

    attn_kernel<<<dim3(T_LEN / 16, HQ), 128>>>(Q, Kp, Vp, Yp);

    sgemm128<<<dim3(C_DIM / 128, T_LEN / 128), 256>>>(Yp, Wo, out, T_LEN, C_DIM, C_DIM);
}

// round 3
// speedup vs baseline: 1.1018x; 1.1018x over previous
#include <cuda_runtime.h>
#include <cuda_bf16.h>
#include <math.h>
#include <float.h>
#include <stdint.h>

// Problem constants
#define T_LEN   4096
#define C_DIM   2048
#define HQ      16
#define HKV     4
#define HD      128
#define WIN     1024

// Scratch (device globals; no allocations allowed)
__device__ float g_Q[T_LEN * HQ * HD];     // 4096 x 2048
__device__ float g_K[T_LEN * HKV * HD];    // 4096 x 512
__device__ float g_V[T_LEN * HKV * HD];    // 4096 x 512
__device__ float g_Y[T_LEN * HQ * HD];     // 4096 x 2048
__device__ float g_cos[T_LEN * 64];
__device__ float g_sin[T_LEN * 64];

// ---------------------------------------------------------------------------
// bf16x3 split tensor-core GEMM: C[M,N] = A[M,K] * B[K,N], fp32 in/out.
// Split each fp32 into hi+lo bf16; acc += Ahi*Bhi + Ahi*Blo + Alo*Bhi (fp32 acc).
// Block tile 128x128, BK=32, 256 threads (8 warps), warp tile 32x64.
// ---------------------------------------------------------------------------

#define LDMATRIX_X4(R0,R1,R2,R3,ADDR) \
    asm volatile("ldmatrix.sync.aligned.m8n8.x4.shared.b16 {%0,%1,%2,%3}, [%4];" \
        : "=r"(R0), "=r"(R1), "=r"(R2), "=r"(R3) : "r"(ADDR))

#define LDMATRIX_X4_T(R0,R1,R2,R3,ADDR) \
    asm volatile("ldmatrix.sync.aligned.m8n8.x4.trans.shared.b16 {%0,%1,%2,%3}, [%4];" \
        : "=r"(R0), "=r"(R1), "=r"(R2), "=r"(R3) : "r"(ADDR))

#define MMA_BF16(D, A0,A1,A2,A3, B0,B1) \
    asm volatile("mma.sync.aligned.m16n8k16.row.col.f32.bf16.bf16.f32 " \
        "{%0,%1,%2,%3}, {%4,%5,%6,%7}, {%8,%9}, {%0,%1,%2,%3};" \
        : "+f"((D)[0]), "+f"((D)[1]), "+f"((D)[2]), "+f"((D)[3]) \
        : "r"(A0), "r"(A1), "r"(A2), "r"(A3), "r"(B0), "r"(B1))

__device__ __forceinline__ uint32_t smem_u32(const void* p) {
    return (uint32_t)__cvta_generic_to_shared(p);
}

// Smem layout constants (bf16 element strides; padded for conflict-free ldmatrix)
#define A_STRIDE 40    // 128 rows x 40 bf16 (32 used) -> 80B rows
#define B_STRIDE 136   // 32 rows x 136 bf16 (128 used) -> 272B rows
#define A_BUF    (128 * A_STRIDE)      // elements per hi/lo buffer
#define B_BUF    (32 * B_STRIDE)

__global__ __launch_bounds__(256, 2)
void gemm_bf16x3(const float* __restrict__ A, const float* __restrict__ B,
                 float* __restrict__ C, int M, int N, int K)
{
    __shared__ __nv_bfloat16 As[2][A_BUF];   // [0]=hi, [1]=lo
    __shared__ __nv_bfloat16 Bs[2][B_BUF];

    const int tid  = threadIdx.x;
    const int wid  = tid >> 5;
    const int lane = tid & 31;
    const int warp_m = wid & 3;     // 4 warps along M (32 rows each)
    const int warp_n = wid >> 2;    // 2 warps along N (64 cols each)
    const int bx = blockIdx.x, by = blockIdx.y;

    // Global load mapping
    const int arow = tid >> 1;            // 0..127
    const int acol = (tid & 1) << 4;      // 0 or 16
    const int brow = tid >> 3;            // 0..31
    const int bcol = (tid & 7) << 4;      // 0..112

    const float* Ag = A + (size_t)(by * 128 + arow) * K + acol;
    const float* Bg = B + (size_t)brow * N + bx * 128 + bcol;

    float acc[2][8][4];
#pragma unroll
    for (int mi = 0; mi < 2; mi++)
#pragma unroll
        for (int nf = 0; nf < 8; nf++)
#pragma unroll
            for (int e = 0; e < 4; e++) acc[mi][nf][e] = 0.0f;

    // Per-lane ldmatrix base addresses (byte offsets)
    // A (no trans): lanes 0-15 -> rows m0+0..15 (k0..7), lanes 16-31 -> same rows, k8..15
    uint32_t a_base[2];
#pragma unroll
    for (int mi = 0; mi < 2; mi++) {
        int row = warp_m * 32 + mi * 16 + (lane & 15);
        a_base[mi] = smem_u32(As) + (uint32_t)(row * A_STRIDE) * 2 + ((lane >> 4) << 4);
    }
    // B (trans): matrix q <- lanes q*8..q*8+7; rows k = ((lane>>3)&1)*8 + lane%8,
    // col block n0 + (lane>>4)*8
    {
    }
    int b_row = (((lane >> 3) & 1) << 3) + (lane & 7);
    uint32_t b_base = smem_u32(Bs) + (uint32_t)(b_row * B_STRIDE + warp_n * 64) * 2
                      + ((lane >> 4) << 4);

    const uint32_t A_LO_OFF = A_BUF * 2;   // bytes from hi to lo buffer
    const uint32_t B_LO_OFF = B_BUF * 2;

    for (int k0 = 0; k0 < K; k0 += 32) {
        // --- load + split-convert A tile (128x32) ---
#pragma unroll
        for (int i = 0; i < 4; i++) {
            float4 v = *(const float4*)(Ag + k0 + i * 4);
            int off = arow * A_STRIDE + acol + i * 4;
            float h0 = __bfloat162float(__float2bfloat16_rn(v.x));
            float h1 = __bfloat162float(__float2bfloat16_rn(v.y));
            float h2 = __bfloat162float(__float2bfloat16_rn(v.z));
            float h3 = __bfloat162float(__float2bfloat16_rn(v.w));
            *(__nv_bfloat162*)&As[0][off]     = __nv_bfloat162(__float2bfloat16_rn(v.x), __float2bfloat16_rn(v.y));
            *(__nv_bfloat162*)&As[0][off + 2] = __nv_bfloat162(__float2bfloat16_rn(v.z), __float2bfloat16_rn(v.w));
            *(__nv_bfloat162*)&As[1][off]     = __nv_bfloat162(__float2bfloat16_rn(v.x - h0), __float2bfloat16_rn(v.y - h1));
            *(__nv_bfloat162*)&As[1][off + 2] = __nv_bfloat162(__float2bfloat16_rn(v.z - h2), __float2bfloat16_rn(v.w - h3));
        }
        // --- load + split-convert B tile (32x128) ---
#pragma unroll
        for (int i = 0; i < 4; i++) {
            float4 v = *(const float4*)(Bg + (size_t)k0 * N + i * 4);
            int off = brow * B_STRIDE + bcol + i * 4;
            float h0 = __bfloat162float(__float2bfloat16_rn(v.x));
            float h1 = __bfloat162float(__float2bfloat16_rn(v.y));
            float h2 = __bfloat162float(__float2bfloat16_rn(v.z));
            float h3 = __bfloat162float(__float2bfloat16_rn(v.w));
            *(__nv_bfloat162*)&Bs[0][off]     = __nv_bfloat162(__float2bfloat16_rn(v.x), __float2bfloat16_rn(v.y));
            *(__nv_bfloat162*)&Bs[0][off + 2] = __nv_bfloat162(__float2bfloat16_rn(v.z), __float2bfloat16_rn(v.w));
            *(__nv_bfloat162*)&Bs[1][off]     = __nv_bfloat162(__float2bfloat16_rn(v.x - h0), __float2bfloat16_rn(v.y - h1));
            *(__nv_bfloat162*)&Bs[1][off + 2] = __nv_bfloat162(__float2bfloat16_rn(v.z - h2), __float2bfloat16_rn(v.w - h3));
        }
        __syncthreads();

#pragma unroll
        for (int ks = 0; ks < 2; ks++) {
            // A fragments: 2 m-tiles x {hi,lo}
            uint32_t ahi[2][4], alo[2][4];
#pragma unroll
            for (int mi = 0; mi < 2; mi++) {
                uint32_t ad = a_base[mi] + ks * 32;
                LDMATRIX_X4(ahi[mi][0], ahi[mi][1], ahi[mi][2], ahi[mi][3], ad);
                LDMATRIX_X4(alo[mi][0], alo[mi][1], alo[mi][2], alo[mi][3], ad + A_LO_OFF);
            }
#pragma unroll
            for (int ng = 0; ng < 4; ng++) {
                uint32_t bhi[4], blo[4];
                uint32_t bd = b_base + (uint32_t)(ks * 16 * B_STRIDE + ng * 16) * 2;
                LDMATRIX_X4_T(bhi[0], bhi[1], bhi[2], bhi[3], bd);
                LDMATRIX_X4_T(blo[0], blo[1], blo[2], blo[3], bd + B_LO_OFF);
#pragma unroll
                for (int mi = 0; mi < 2; mi++) {
                    int nf = ng * 2;
                    MMA_BF16(acc[mi][nf],   ahi[mi][0], ahi[mi][1], ahi[mi][2], ahi[mi][3], bhi[0], bhi[1]);
                    MMA_BF16(acc[mi][nf],   ahi[mi][0], ahi[mi][1], ahi[mi][2], ahi[mi][3], blo[0], blo[1]);
                    MMA_BF16(acc[mi][nf],   alo[mi][0], alo[mi][1], alo[mi][2], alo[mi][3], bhi[0], bhi[1]);
                    MMA_BF16(acc[mi][nf+1], ahi[mi][0], ahi[mi][1], ahi[mi][2], ahi[mi][3], bhi[2], bhi[3]);
                    MMA_BF16(acc[mi][nf+1], ahi[mi][0], ahi[mi][1], ahi[mi][2], ahi[mi][3], blo[2], blo[3]);
                    MMA_BF16(acc[mi][nf+1], alo[mi][0], alo[mi][1], alo[mi][2], alo[mi][3], bhi[2], bhi[3]);
                }
            }
        }
        __syncthreads();
    }

    // Epilogue: m16n8 acc layout: c0,c1 at (trow, tcol..tcol+1), c2,c3 at (trow+8, ...)
    const int trow = lane >> 2;
    const int tcol = (lane & 3) << 1;
#pragma unroll
    for (int mi = 0; mi < 2; mi++) {
#pragma unroll
        for (int nf = 0; nf < 8; nf++) {
            int rg = by * 128 + warp_m * 32 + mi * 16 + trow;
            int cg = bx * 128 + warp_n * 64 + nf * 8 + tcol;
            *(float2*)&C[(size_t)rg * N + cg]       = make_float2(acc[mi][nf][0], acc[mi][nf][1]);
            *(float2*)&C[(size_t)(rg + 8) * N + cg] = make_float2(acc[mi][nf][2], acc[mi][nf][3]);
        }
    }
}

// ---------------------------------------------------------------------------
// RoPE cos/sin table (fp32 angle rounding like reference; fp64 trig).
// ---------------------------------------------------------------------------
__global__ void rope_table_kernel()
{
    int idx = blockIdx.x * blockDim.x + threadIdx.x;
    if (idx >= T_LEN * 64) return;
    int t = idx >> 6;
    int j = idx & 63;
    double e = exp(-(double)j * (log(10000.0) / 64.0));
    float invf = (float)e;
    float ang = (float)t * invf;
    double a = (double)ang;
    g_cos[idx] = (float)cos(a);
    g_sin[idx] = (float)sin(a);
}

// Apply RoPE in-place to Q [T, HQ*HD] and K [T, HKV*HD].
__global__ void rope_apply_kernel(float* __restrict__ Q, float* __restrict__ K)
{
    const int NQ = T_LEN * HQ * 64;
    int idx = blockIdx.x * blockDim.x + threadIdx.x;
    float* p;
    int t, j;
    if (idx < NQ) {
        t = idx >> 10;
        int rem = idx & 1023;
        int h = rem >> 6;
        j = rem & 63;
        p = Q + (size_t)t * (HQ * HD) + h * HD;
    } else {
        int i2 = idx - NQ;
        t = i2 >> 8;
        int rem = i2 & 255;
        int h = rem >> 6;
        j = rem & 63;
        p = K + (size_t)t * (HKV * HD) + h * HD;
    }
    float cv = g_cos[t * 64 + j];
    float sv = g_sin[t * 64 + j];
    float x0 = p[j];
    float x1 = p[j + 64];
    p[j]      = x0 * cv - x1 * sv;
    p[j + 64] = x1 * cv + x0 * sv;
}

// ---------------------------------------------------------------------------
// Sliding-window causal attention, fp32, branchless online softmax.
// Grid: (T/16, HQ). Block: 128 threads. Tile: 16 q x 32 k.
// ---------------------------------------------------------------------------
__global__ __launch_bounds__(128)
void attn_kernel(const float* __restrict__ Q, const float* __restrict__ K,
                 const float* __restrict__ V, float* __restrict__ Y)
{
    const int BQ = 16, BK = 32;
    __shared__ float Qs[BQ][HD];
    __shared__ float Ks[BK][HD];
    __shared__ float Vs[BK][HD];
    __shared__ float Ps[BQ][BK];

    const int qb = blockIdx.x;
    const int h  = blockIdx.y;
    const int kvh = h >> 2;

    const int tid = threadIdx.x;
    const int r = tid >> 3;
    const int c = tid & 7;
    const int d0 = c * 16;

    const int q_i = qb * BQ + r;

#pragma unroll
    for (int it = 0; it < 4; it++) {
        int idx4 = tid + 128 * it;
        int row = idx4 >> 5;
        int dd4 = idx4 & 31;
        int t = qb * BQ + row;
        float4 qv = *(const float4*)(Q + (size_t)t * (HQ * HD) + h * HD + dd4 * 4);
        *(float4*)&Qs[row][dd4 * 4] = qv;
    }

    float o[16];
#pragma unroll
    for (int i = 0; i < 16; i++) o[i] = 0.0f;
    float m = -INFINITY;
    float l = 0.0f;

    int j_min = qb * BQ - (WIN - 1);
    if (j_min < 0) j_min = 0;
    const int kb0 = j_min / BK;
    const int kb1 = (qb * BQ + BQ - 1) / BK;

    const float sc = 0.08838834764831845f;

    for (int kb = kb0; kb <= kb1; kb++) {
        const int jbase = kb * BK;
#pragma unroll
        for (int it = 0; it < 8; it++) {
            int idx4 = tid + 128 * it;
            int row = idx4 >> 5;
            int dd4 = idx4 & 31;
            size_t goff = (size_t)(jbase + row) * (HKV * HD) + kvh * HD + dd4 * 4;
            *(float4*)&Ks[row][dd4 * 4] = *(const float4*)(K + goff);
            *(float4*)&Vs[row][dd4 * 4] = *(const float4*)(V + goff);
        }
        __syncthreads();

        float s0 = 0.f, s1 = 0.f, s2 = 0.f, s3 = 0.f;
#pragma unroll
        for (int d4 = 0; d4 < 32; d4++) {
            float4 q  = *(const float4*)&Qs[r][d4 * 4];
            float4 k0 = *(const float4*)&Ks[c][d4 * 4];
            float4 k1 = *(const float4*)&Ks[c + 8][d4 * 4];
            float4 k2 = *(const float4*)&Ks[c + 16][d4 * 4];
            float4 k3 = *(const float4*)&Ks[c + 24][d4 * 4];
            s0 += q.x * k0.x + q.y * k0.y + q.z * k0.z + q.w * k0.w;
            s1 += q.x * k1.x + q.y * k1.y + q.z * k1.z + q.w * k1.w;
            s2 += q.x * k2.x + q.y * k2.y + q.z * k2.z + q.w * k2.w;
            s3 += q.x * k3.x + q.y * k3.y + q.z * k3.z + q.w * k3.w;
        }

        float sv[4] = { s0 * sc, s1 * sc, s2 * sc, s3 * sc };
#pragma unroll
        for (int u = 0; u < 4; u++) {
            int j = jbase + c + 8 * u;
            bool ok = (j <= q_i) && ((q_i - j) < WIN);
            if (!ok) sv[u] = -INFINITY;
        }

        float bm = fmaxf(fmaxf(sv[0], sv[1]), fmaxf(sv[2], sv[3]));
#pragma unroll
        for (int off = 4; off >= 1; off >>= 1)
            bm = fmaxf(bm, __shfl_xor_sync(0xffffffffu, bm, off));

        float m_new = fmaxf(m, bm);
        float mm = (m_new == -INFINITY) ? 0.0f : m_new;
        float factor = expf(m - mm);
        float p0 = expf(sv[0] - mm);
        float p1 = expf(sv[1] - mm);
        float p2 = expf(sv[2] - mm);
        float p3 = expf(sv[3] - mm);
        float psum = p0 + p1 + p2 + p3;
#pragma unroll
        for (int off = 4; off >= 1; off >>= 1)
            psum += __shfl_xor_sync(0xffffffffu, psum, off);
        l = l * factor + psum;
        m = m_new;
#pragma unroll
        for (int i = 0; i < 16; i++) o[i] *= factor;
        Ps[r][c]      = p0;
        Ps[r][c + 8]  = p1;
        Ps[r][c + 16] = p2;
        Ps[r][c + 24] = p3;
        __syncthreads();

#pragma unroll
        for (int k = 0; k < BK; k++) {
            float p = Ps[r][k];
            float4 v0 = *(const float4*)&Vs[k][d0];
            float4 v1 = *(const float4*)&Vs[k][d0 + 4];
            float4 v2 = *(const float4*)&Vs[k][d0 + 8];
            float4 v3 = *(const float4*)&Vs[k][d0 + 12];
            o[0]  += p * v0.x; o[1]  += p * v0.y; o[2]  += p * v0.z; o[3]  += p * v0.w;
            o[4]  += p * v1.x; o[5]  += p * v1.y; o[6]  += p * v1.z; o[7]  += p * v1.w;
            o[8]  += p * v2.x; o[9]  += p * v2.y; o[10] += p * v2.z; o[11] += p * v2.w;
            o[12] += p * v3.x; o[13] += p * v3.y; o[14] += p * v3.z; o[15] += p * v3.w;
        }
        __syncthreads();
    }

    float inv_l = 1.0f / l;
    float* yp = Y + (size_t)q_i * (HQ * HD) + h * HD + d0;
#pragma unroll
    for (int i4 = 0; i4 < 4; i4++) {
        float4 w = make_float4(o[i4 * 4 + 0] * inv_l, o[i4 * 4 + 1] * inv_l,
                               o[i4 * 4 + 2] * inv_l, o[i4 * 4 + 3] * inv_l);
        *(float4*)(yp + i4 * 4) = w;
    }
}

// ---------------------------------------------------------------------------
// Launch
// ---------------------------------------------------------------------------
extern "C" void kernel_launch(void* const* d_in, const int* in_sizes, int n_in,
                              void* d_out, int out_size)
{
    const float* x  = (const float*)d_in[0];
    const float* Wq = (const float*)d_in[1];
    const float* Wk = (const float*)d_in[2];
    const float* Wv = (const float*)d_in[3];
    const float* Wo = (const float*)d_in[4];
    float* out = (float*)d_out;

    float *Q, *Kp, *Vp, *Yp;
    cudaGetSymbolAddress((void**)&Q,  g_Q);
    cudaGetSymbolAddress((void**)&Kp, g_K);
    cudaGetSymbolAddress((void**)&Vp, g_V);
    cudaGetSymbolAddress((void**)&Yp, g_Y);

    // Projections (bf16x3 tensor-core GEMMs)
    gemm_bf16x3<<<dim3((HQ * HD) / 128, T_LEN / 128), 256>>>(x, Wq, Q,  T_LEN, HQ * HD,  C_DIM);
    gemm_bf16x3<<<dim3((HKV * HD) / 128, T_LEN / 128), 256>>>(x, Wk, Kp, T_LEN, HKV * HD, C_DIM);
    gemm_bf16x3<<<dim3((HKV * HD) / 128, T_LEN / 128), 256>>>(x, Wv, Vp, T_LEN, HKV * HD, C_DIM);

    // RoPE
    rope_table_kernel<<<(T_LEN * 64 + 255) / 256, 256>>>();
    const int n_rope = T_LEN * HQ * 64 + T_LEN * HKV * 64;
    rope_apply_kernel<<<n_rope / 256, 256>>>(Q, Kp);

    // Attention
    attn_kernel<<<dim3(T_LEN / 16, HQ), 128>>>(Q, Kp, Vp, Yp);

    // Output projection
    gemm_bf16x3<<<dim3(C_DIM / 128, T_LEN / 128), 256>>>(Yp, Wo, out, T_LEN, C_DIM, C_DIM);
}

// round 4
// speedup vs baseline: 8.7466x; 7.9385x over previous
#include <cuda_runtime.h>
#include <cuda_bf16.h>
#include <math.h>
#include <float.h>
#include <stdint.h>

// Problem constants
#define T_LEN   4096
#define C_DIM   2048
#define HQ      16
#define HKV     4
#define HD      128
#define WIN     1024

// Scratch (device globals; no allocations allowed)
__device__ float g_Q[T_LEN * HQ * HD];     // 4096 x 2048
__device__ float g_K[T_LEN * HKV * HD];    // 4096 x 512
__device__ float g_V[T_LEN * HKV * HD];    // 4096 x 512
__device__ float g_Y[T_LEN * HQ * HD];     // 4096 x 2048
__device__ float g_cos[T_LEN * 64];
__device__ float g_sin[T_LEN * 64];

// ---------------------------------------------------------------------------
// Common MMA helpers
// ---------------------------------------------------------------------------
#define LDMATRIX_X4(R0,R1,R2,R3,ADDR) \
    asm volatile("ldmatrix.sync.aligned.m8n8.x4.shared.b16 {%0,%1,%2,%3}, [%4];" \
        : "=r"(R0), "=r"(R1), "=r"(R2), "=r"(R3) : "r"(ADDR))

#define LDMATRIX_X4_T(R0,R1,R2,R3,ADDR) \
    asm volatile("ldmatrix.sync.aligned.m8n8.x4.trans.shared.b16 {%0,%1,%2,%3}, [%4];" \
        : "=r"(R0), "=r"(R1), "=r"(R2), "=r"(R3) : "r"(ADDR))

#define MMA_BF16(D, A0,A1,A2,A3, B0,B1) \
    asm volatile("mma.sync.aligned.m16n8k16.row.col.f32.bf16.bf16.f32 " \
        "{%0,%1,%2,%3}, {%4,%5,%6,%7}, {%8,%9}, {%0,%1,%2,%3};" \
        : "+f"((D)[0]), "+f"((D)[1]), "+f"((D)[2]), "+f"((D)[3]) \
        : "r"(A0), "r"(A1), "r"(A2), "r"(A3), "r"(B0), "r"(B1))

__device__ __forceinline__ uint32_t smem_u32(const void* p) {
    return (uint32_t)__cvta_generic_to_shared(p);
}

// Split two fp32 into bf16x2 hi and bf16x2 lo (packed, memory order: a=low half)
__device__ __forceinline__ void split2(float a, float b, uint32_t& hi, uint32_t& lo) {
    __nv_bfloat16 ah = __float2bfloat16_rn(a);
    __nv_bfloat16 bh = __float2bfloat16_rn(b);
    __nv_bfloat162 h(ah, bh);
    hi = *(uint32_t*)&h;
    __nv_bfloat162 l(__float2bfloat16_rn(a - __bfloat162float(ah)),
                     __float2bfloat16_rn(b - __bfloat162float(bh)));
    lo = *(uint32_t*)&l;
}

// ---------------------------------------------------------------------------
// bf16x3 split tensor-core GEMM: C[M,N] = A[M,K]*B[K,N], fp32 in/out.
// 128x128 block tile, BK=32, 256 threads, warp tile 32x64.
// Register-prefetch software pipeline to hide LDG latency.
// ---------------------------------------------------------------------------
#define A_STRIDE 40    // bf16 elems per A row (32 used), 80B rows
#define B_STRIDE 136   // bf16 elems per B row (128 used), 272B rows
#define A_BUF    (128 * A_STRIDE)
#define B_BUF    (32 * B_STRIDE)

__global__ __launch_bounds__(256)
void gemm_bf16x3(const float* __restrict__ A, const float* __restrict__ B,
                 float* __restrict__ C, int M, int N, int K)
{
    __shared__ __nv_bfloat16 As[2][A_BUF];   // [0]=hi, [1]=lo
    __shared__ __nv_bfloat16 Bs[2][B_BUF];

    const int tid  = threadIdx.x;
    const int wid  = tid >> 5;
    const int lane = tid & 31;
    const int warp_m = wid & 3;
    const int warp_n = wid >> 2;
    const int bx = blockIdx.x, by = blockIdx.y;

    const int arow = tid >> 1;
    const int acol = (tid & 1) << 4;
    const int brow = tid >> 3;
    const int bcol = (tid & 7) << 4;

    const float* Ag = A + (size_t)(by * 128 + arow) * K + acol;
    const float* Bg = B + (size_t)brow * N + bx * 128 + bcol;

    float acc[2][8][4];
#pragma unroll
    for (int mi = 0; mi < 2; mi++)
#pragma unroll
        for (int nf = 0; nf < 8; nf++)
#pragma unroll
            for (int e = 0; e < 4; e++) acc[mi][nf][e] = 0.0f;

    uint32_t a_base[2];
#pragma unroll
    for (int mi = 0; mi < 2; mi++) {
        int row = warp_m * 32 + mi * 16 + (lane & 15);
        a_base[mi] = smem_u32(As) + (uint32_t)(row * A_STRIDE) * 2 + ((lane >> 4) << 4);
    }
    int b_row = (((lane >> 3) & 1) << 3) + (lane & 7);
    uint32_t b_base = smem_u32(Bs) + (uint32_t)(b_row * B_STRIDE + warp_n * 64) * 2
                      + ((lane >> 4) << 4);

    const uint32_t A_LO_OFF = A_BUF * 2;
    const uint32_t B_LO_OFF = B_BUF * 2;

    // Prologue: prefetch first tile into registers
    float4 pa[4], pb[4];
#pragma unroll
    for (int i = 0; i < 4; i++) {
        pa[i] = *(const float4*)(Ag + i * 4);
        pb[i] = *(const float4*)(Bg + i * 4);
    }

    for (int k0 = 0; k0 < K; k0 += 32) {
        // Store current tile (with hi/lo split) to smem
#pragma unroll
        for (int i = 0; i < 4; i++) {
            int offA = arow * A_STRIDE + acol + i * 4;
            uint32_t h0, l0, h1, l1;
            split2(pa[i].x, pa[i].y, h0, l0);
            split2(pa[i].z, pa[i].w, h1, l1);
            *(uint32_t*)&As[0][offA]     = h0;
            *(uint32_t*)&As[0][offA + 2] = h1;
            *(uint32_t*)&As[1][offA]     = l0;
            *(uint32_t*)&As[1][offA + 2] = l1;
            int offB = brow * B_STRIDE + bcol + i * 4;
            split2(pb[i].x, pb[i].y, h0, l0);
            split2(pb[i].z, pb[i].w, h1, l1);
            *(uint32_t*)&Bs[0][offB]     = h0;
            *(uint32_t*)&Bs[0][offB + 2] = h1;
            *(uint32_t*)&Bs[1][offB]     = l0;
            *(uint32_t*)&Bs[1][offB + 2] = l1;
        }
        __syncthreads();

        // Prefetch next tile while computing this one
        if (k0 + 32 < K) {
#pragma unroll
            for (int i = 0; i < 4; i++) {
                pa[i] = *(const float4*)(Ag + k0 + 32 + i * 4);
                pb[i] = *(const float4*)(Bg + (size_t)(k0 + 32) * N + i * 4);
            }
        }

#pragma unroll
        for (int ks = 0; ks < 2; ks++) {
            uint32_t ahi[2][4], alo[2][4];
#pragma unroll
            for (int mi = 0; mi < 2; mi++) {
                uint32_t ad = a_base[mi] + ks * 32;
                LDMATRIX_X4(ahi[mi][0], ahi[mi][1], ahi[mi][2], ahi[mi][3], ad);
                LDMATRIX_X4(alo[mi][0], alo[mi][1], alo[mi][2], alo[mi][3], ad + A_LO_OFF);
            }
#pragma unroll
            for (int ng = 0; ng < 4; ng++) {
                uint32_t bhi[4], blo[4];
                uint32_t bd = b_base + (uint32_t)(ks * 16 * B_STRIDE + ng * 16) * 2;
                LDMATRIX_X4_T(bhi[0], bhi[1], bhi[2], bhi[3], bd);
                LDMATRIX_X4_T(blo[0], blo[1], blo[2], blo[3], bd + B_LO_OFF);
#pragma unroll
                for (int mi = 0; mi < 2; mi++) {
                    int nf = ng * 2;
                    MMA_BF16(acc[mi][nf],   ahi[mi][0], ahi[mi][1], ahi[mi][2], ahi[mi][3], bhi[0], bhi[1]);
                    MMA_BF16(acc[mi][nf],   ahi[mi][0], ahi[mi][1], ahi[mi][2], ahi[mi][3], blo[0], blo[1]);
                    MMA_BF16(acc[mi][nf],   alo[mi][0], alo[mi][1], alo[mi][2], alo[mi][3], bhi[0], bhi[1]);
                    MMA_BF16(acc[mi][nf+1], ahi[mi][0], ahi[mi][1], ahi[mi][2], ahi[mi][3], bhi[2], bhi[3]);
                    MMA_BF16(acc[mi][nf+1], ahi[mi][0], ahi[mi][1], ahi[mi][2], ahi[mi][3], blo[2], blo[3]);
                    MMA_BF16(acc[mi][nf+1], alo[mi][0], alo[mi][1], alo[mi][2], alo[mi][3], bhi[2], bhi[3]);
                }
            }
        }
        __syncthreads();
    }

    const int trow = lane >> 2;
    const int tcol = (lane & 3) << 1;
#pragma unroll
    for (int mi = 0; mi < 2; mi++) {
#pragma unroll
        for (int nf = 0; nf < 8; nf++) {
            int rg = by * 128 + warp_m * 32 + mi * 16 + trow;
            int cg = bx * 128 + warp_n * 64 + nf * 8 + tcol;
            *(float2*)&C[(size_t)rg * N + cg]       = make_float2(acc[mi][nf][0], acc[mi][nf][1]);
            *(float2*)&C[(size_t)(rg + 8) * N + cg] = make_float2(acc[mi][nf][2], acc[mi][nf][3]);
        }
    }
}

// ---------------------------------------------------------------------------
// RoPE cos/sin table (fp32 angle rounding like reference; fp64 trig).
// ---------------------------------------------------------------------------
__global__ void rope_table_kernel()
{
    int idx = blockIdx.x * blockDim.x + threadIdx.x;
    if (idx >= T_LEN * 64) return;
    int t = idx >> 6;
    int j = idx & 63;
    double e = exp(-(double)j * (log(10000.0) / 64.0));
    float invf = (float)e;
    float ang = (float)t * invf;
    double a = (double)ang;
    g_cos[idx] = (float)cos(a);
    g_sin[idx] = (float)sin(a);
}

__global__ void rope_apply_kernel(float* __restrict__ Q, float* __restrict__ K)
{
    const int NQ = T_LEN * HQ * 64;
    int idx = blockIdx.x * blockDim.x + threadIdx.x;
    float* p;
    int t, j;
    if (idx < NQ) {
        t = idx >> 10;
        int rem = idx & 1023;
        int h = rem >> 6;
        j = rem & 63;
        p = Q + (size_t)t * (HQ * HD) + h * HD;
    } else {
        int i2 = idx - NQ;
        t = i2 >> 8;
        int rem = i2 & 255;
        int h = rem >> 6;
        j = rem & 63;
        p = K + (size_t)t * (HKV * HD) + h * HD;
    }
    float cv = g_cos[t * 64 + j];
    float sv = g_sin[t * 64 + j];
    float x0 = p[j];
    float x1 = p[j + 64];
    p[j]      = x0 * cv - x1 * sv;
    p[j + 64] = x1 * cv + x0 * sv;
}

// ---------------------------------------------------------------------------
// Tensor-core flash attention with sliding window.
// Grid: (T/64, HQ). Block: 128 threads (4 warps, 16 q-rows each).
// K/V tiles of 32 keys, bf16 hi/lo split in smem; Q fragments in registers.
// QK^T and PV via mma.m16n8k16 with 3-term hi/lo products (fp32 acc).
// Branchless exp2-based online softmax.
// ---------------------------------------------------------------------------
#define KVS 136   // bf16 elems per smem row (128 + 8 pad -> 272B rows)

__global__ __launch_bounds__(128)
void attn_tc_kernel(const float* __restrict__ Q, const float* __restrict__ K,
                    const float* __restrict__ V, float* __restrict__ Y)
{
    __shared__ __nv_bfloat16 Kh[32][KVS];
    __shared__ __nv_bfloat16 Kl[32][KVS];
    __shared__ __nv_bfloat16 Vh[32][KVS];
    __shared__ __nv_bfloat16 Vl[32][KVS];

    const int qb  = blockIdx.x;
    const int h   = blockIdx.y;
    const int kvh = h >> 2;
    const int tid  = threadIdx.x;
    const int wid  = tid >> 5;
    const int lane = tid & 31;
    const int trow = lane >> 2;
    const int tc2  = (lane & 3) << 1;
    const int qrow0 = qb * 64 + wid * 16;

    // ---- Q fragments (RoPE already applied), hi/lo split, in registers ----
    uint32_t qhi[8][4], qlo[8][4];
#pragma unroll
    for (int ks = 0; ks < 8; ks++) {
#pragma unroll
        for (int r = 0; r < 4; r++) {
            int row = qrow0 + trow + ((r & 1) << 3);
            int d = ks * 16 + ((r >> 1) << 3) + tc2;
            float2 v = *(const float2*)(Q + (size_t)row * (HQ * HD) + h * HD + d);
            split2(v.x, v.y, qhi[ks][r], qlo[ks][r]);
        }
    }

    float oacc[16][4];
#pragma unroll
    for (int nf = 0; nf < 16; nf++)
#pragma unroll
        for (int e = 0; e < 4; e++) oacc[nf][e] = 0.0f;
    float m2[2]   = { -1e30f, -1e30f };   // running max (base-2 scaled domain)
    float lsum[2] = { 0.0f, 0.0f };

    int jmin = qb * 64 - (WIN - 1);
    if (jmin < 0) jmin = 0;
    const int kb0 = jmin >> 5;
    const int kb1 = (qb * 64 + 63) >> 5;

    // ldmatrix lane addressing
    const int krow    = (lane & 7) + ((lane >> 4) << 3);   // K (non-trans B)
    const int kcoloff = ((lane >> 3) & 1) << 3;            // halves
    const int vrow    = (lane & 7) + (((lane >> 3) & 1) << 3);  // V (trans B)
    const int vcoloff = (lane >> 4) << 3;                  // halves

    const uint32_t kh_base = smem_u32(Kh) + (uint32_t)(krow * KVS + kcoloff) * 2;
    const uint32_t kl_base = smem_u32(Kl) + (uint32_t)(krow * KVS + kcoloff) * 2;
    const uint32_t vh_base = smem_u32(Vh) + (uint32_t)(vrow * KVS + vcoloff) * 2;
    const uint32_t vl_base = smem_u32(Vl) + (uint32_t)(vrow * KVS + vcoloff) * 2;
    const uint32_t KROW16 = (uint32_t)(16 * KVS) * 2;      // 16 rows in bytes

    const float SC = (float)(0.08838834764831845 * 1.4426950408889634); // 1/sqrt(128)*log2(e)

    for (int kb = kb0; kb <= kb1; kb++) {
        const int jb = kb * 32;
        __syncthreads();   // previous tile's compute done before overwrite
        // ---- load K/V tile (32x128), split to bf16 hi/lo ----
#pragma unroll
        for (int i = 0; i < 8; i++) {
            int f4  = tid + 128 * i;
            int row = f4 >> 5;
            int c4  = (f4 & 31) << 2;
            size_t g = (size_t)(jb + row) * (HKV * HD) + kvh * HD + c4;
            float4 kx = *(const float4*)(K + g);
            uint32_t h0, l0, h1, l1;
            split2(kx.x, kx.y, h0, l0);
            split2(kx.z, kx.w, h1, l1);
            *(uint32_t*)&Kh[row][c4]     = h0;
            *(uint32_t*)&Kh[row][c4 + 2] = h1;
            *(uint32_t*)&Kl[row][c4]     = l0;
            *(uint32_t*)&Kl[row][c4 + 2] = l1;
            float4 vx = *(const float4*)(V + g);
            split2(vx.x, vx.y, h0, l0);
            split2(vx.z, vx.w, h1, l1);
            *(uint32_t*)&Vh[row][c4]     = h0;
            *(uint32_t*)&Vh[row][c4 + 2] = h1;
            *(uint32_t*)&Vl[row][c4]     = l0;
            *(uint32_t*)&Vl[row][c4 + 2] = l1;
        }
        __syncthreads();

        // ---- S = Q K^T (bf16x3) ----
        float sacc[4][4];
#pragma unroll
        for (int f = 0; f < 4; f++)
#pragma unroll
            for (int e = 0; e < 4; e++) sacc[f][e] = 0.0f;

#pragma unroll
        for (int ks = 0; ks < 8; ks++) {
            uint32_t off = (uint32_t)(ks * 16) * 2;
            uint32_t bh0[4], bh1[4], bl0[4], bl1[4];
            LDMATRIX_X4(bh0[0], bh0[1], bh0[2], bh0[3], kh_base + off);
            LDMATRIX_X4(bh1[0], bh1[1], bh1[2], bh1[3], kh_base + off + KROW16);
            LDMATRIX_X4(bl0[0], bl0[1], bl0[2], bl0[3], kl_base + off);
            LDMATRIX_X4(bl1[0], bl1[1], bl1[2], bl1[3], kl_base + off + KROW16);
            MMA_BF16(sacc[0], qhi[ks][0], qhi[ks][1], qhi[ks][2], qhi[ks][3], bh0[0], bh0[1]);
            MMA_BF16(sacc[0], qlo[ks][0], qlo[ks][1], qlo[ks][2], qlo[ks][3], bh0[0], bh0[1]);
            MMA_BF16(sacc[0], qhi[ks][0], qhi[ks][1], qhi[ks][2], qhi[ks][3], bl0[0], bl0[1]);
            MMA_BF16(sacc[1], qhi[ks][0], qhi[ks][1], qhi[ks][2], qhi[ks][3], bh0[2], bh0[3]);
            MMA_BF16(sacc[1], qlo[ks][0], qlo[ks][1], qlo[ks][2], qlo[ks][3], bh0[2], bh0[3]);
            MMA_BF16(sacc[1], qhi[ks][0], qhi[ks][1], qhi[ks][2], qhi[ks][3], bl0[2], bl0[3]);
            MMA_BF16(sacc[2], qhi[ks][0], qhi[ks][1], qhi[ks][2], qhi[ks][3], bh1[0], bh1[1]);
            MMA_BF16(sacc[2], qlo[ks][0], qlo[ks][1], qlo[ks][2], qlo[ks][3], bh1[0], bh1[1]);
            MMA_BF16(sacc[2], qhi[ks][0], qhi[ks][1], qhi[ks][2], qhi[ks][3], bl1[0], bl1[1]);
            MMA_BF16(sacc[3], qhi[ks][0], qhi[ks][1], qhi[ks][2], qhi[ks][3], bh1[2], bh1[3]);
            MMA_BF16(sacc[3], qlo[ks][0], qlo[ks][1], qlo[ks][2], qlo[ks][3], bh1[2], bh1[3]);
            MMA_BF16(sacc[3], qhi[ks][0], qhi[ks][1], qhi[ks][2], qhi[ks][3], bl1[2], bl1[3]);
        }

        // ---- masked online softmax (branchless, base-2 domain) ----
        float bm0 = -1e30f, bm1 = -1e30f;
#pragma unroll
        for (int f = 0; f < 4; f++) {
            int j0 = jb + f * 8 + tc2;
#pragma unroll
            for (int e = 0; e < 4; e++) {
                int j  = j0 + (e & 1);
                int qi = qrow0 + trow + ((e >> 1) << 3);
                bool ok = (j <= qi) && ((qi - j) < WIN);
                float s = ok ? sacc[f][e] * SC : -1e30f;
                sacc[f][e] = s;
                if (e < 2) bm0 = fmaxf(bm0, s); else bm1 = fmaxf(bm1, s);
            }
        }
        bm0 = fmaxf(bm0, __shfl_xor_sync(0xffffffffu, bm0, 1));
        bm0 = fmaxf(bm0, __shfl_xor_sync(0xffffffffu, bm0, 2));
        bm1 = fmaxf(bm1, __shfl_xor_sync(0xffffffffu, bm1, 1));
        bm1 = fmaxf(bm1, __shfl_xor_sync(0xffffffffu, bm1, 2));

        float mn0 = fmaxf(m2[0], bm0);
        float mn1 = fmaxf(m2[1], bm1);
        float mm0 = fmaxf(mn0, -1e20f);   // safe offset: fully-masked rows -> p = 0
        float mm1 = fmaxf(mn1, -1e20f);
        float f0 = exp2f(m2[0] - mm0);
        float f1 = exp2f(m2[1] - mm1);
        m2[0] = mn0; m2[1] = mn1;

        float ps0 = 0.0f, ps1 = 0.0f;
#pragma unroll
        for (int f = 0; f < 4; f++) {
            sacc[f][0] = exp2f(sacc[f][0] - mm0);
            sacc[f][1] = exp2f(sacc[f][1] - mm0);
            sacc[f][2] = exp2f(sacc[f][2] - mm1);
            sacc[f][3] = exp2f(sacc[f][3] - mm1);
            ps0 += sacc[f][0] + sacc[f][1];
            ps1 += sacc[f][2] + sacc[f][3];
        }
        ps0 += __shfl_xor_sync(0xffffffffu, ps0, 1);
        ps0 += __shfl_xor_sync(0xffffffffu, ps0, 2);
        ps1 += __shfl_xor_sync(0xffffffffu, ps1, 1);
        ps1 += __shfl_xor_sync(0xffffffffu, ps1, 2);
        lsum[0] = lsum[0] * f0 + ps0;
        lsum[1] = lsum[1] * f1 + ps1;

#pragma unroll
        for (int nf = 0; nf < 16; nf++) {
            oacc[nf][0] *= f0; oacc[nf][1] *= f0;
            oacc[nf][2] *= f1; oacc[nf][3] *= f1;
        }

        // ---- P fragments (hi/lo split) ----
        uint32_t phi[2][4], plo[2][4];
#pragma unroll
        for (int kp = 0; kp < 2; kp++) {
            split2(sacc[2*kp][0],   sacc[2*kp][1],   phi[kp][0], plo[kp][0]);
            split2(sacc[2*kp][2],   sacc[2*kp][3],   phi[kp][1], plo[kp][1]);
            split2(sacc[2*kp+1][0], sacc[2*kp+1][1], phi[kp][2], plo[kp][2]);
            split2(sacc[2*kp+1][2], sacc[2*kp+1][3], phi[kp][3], plo[kp][3]);
        }

        // ---- O += P V (bf16x3) ----
#pragma unroll
        for (int kp = 0; kp < 2; kp++) {
            uint32_t rowoff = (uint32_t)(kp * 16 * KVS) * 2;
#pragma unroll
            for (int ng = 0; ng < 8; ng++) {
                uint32_t coff = rowoff + (uint32_t)(ng * 16) * 2;
                uint32_t vh4[4], vl4[4];
                LDMATRIX_X4_T(vh4[0], vh4[1], vh4[2], vh4[3], vh_base + coff);
                LDMATRIX_X4_T(vl4[0], vl4[1], vl4[2], vl4[3], vl_base + coff);
                MMA_BF16(oacc[2*ng],   phi[kp][0], phi[kp][1], phi[kp][2], phi[kp][3], vh4[0], vh4[1]);
                MMA_BF16(oacc[2*ng],   phi[kp][0], phi[kp][1], phi[kp][2], phi[kp][3], vl4[0], vl4[1]);
                MMA_BF16(oacc[2*ng],   plo[kp][0], plo[kp][1], plo[kp][2], plo[kp][3], vh4[0], vh4[1]);
                MMA_BF16(oacc[2*ng+1], phi[kp][0], phi[kp][1], phi[kp][2], phi[kp][3], vh4[2], vh4[3]);
                MMA_BF16(oacc[2*ng+1], phi[kp][0], phi[kp][1], phi[kp][2], phi[kp][3], vl4[2], vl4[3]);
                MMA_BF16(oacc[2*ng+1], plo[kp][0], plo[kp][1], plo[kp][2], plo[kp][3], vh4[2], vh4[3]);
            }
        }
    }

    // ---- epilogue ----
    float il0 = 1.0f / lsum[0];
    float il1 = 1.0f / lsum[1];
    const int row0 = qrow0 + trow;
#pragma unroll
    for (int nf = 0; nf < 16; nf++) {
        int col = h * HD + nf * 8 + tc2;
        *(float2*)&Y[(size_t)row0 * (HQ * HD) + col] =
            make_float2(oacc[nf][0] * il0, oacc[nf][1] * il0);
        *(float2*)&Y[(size_t)(row0 + 8) * (HQ * HD) + col] =
            make_float2(oacc[nf][2] * il1, oacc[nf][3] * il1);
    }
}

// ---------------------------------------------------------------------------
// Launch (order chosen so launch #4 = big Wq GEMM for ncu capture)
// ---------------------------------------------------------------------------
extern "C" void kernel_launch(void* const* d_in, const int* in_sizes, int n_in,
                              void* d_out, int out_size)
{
    const float* x  = (const float*)d_in[0];
    const float* Wq = (const float*)d_in[1];
    const float* Wk = (const float*)d_in[2];
    const float* Wv = (const float*)d_in[3];
    const float* Wo = (const float*)d_in[4];
    float* out = (float*)d_out;

    float *Q, *Kp, *Vp, *Yp;
    cudaGetSymbolAddress((void**)&Q,  g_Q);
    cudaGetSymbolAddress((void**)&Kp, g_K);
    cudaGetSymbolAddress((void**)&Vp, g_V);
    cudaGetSymbolAddress((void**)&Yp, g_Y);

    // 1: RoPE table (no deps)
    rope_table_kernel<<<(T_LEN * 64 + 255) / 256, 256>>>();
    // 2,3: K,V projections
    gemm_bf16x3<<<dim3((HKV * HD) / 128, T_LEN / 128), 256>>>(x, Wk, Kp, T_LEN, HKV * HD, C_DIM);
    gemm_bf16x3<<<dim3((HKV * HD) / 128, T_LEN / 128), 256>>>(x, Wv, Vp, T_LEN, HKV * HD, C_DIM);
    // 4: Q projection (ncu capture slot)
    gemm_bf16x3<<<dim3((HQ * HD) / 128, T_LEN / 128), 256>>>(x, Wq, Q, T_LEN, HQ * HD, C_DIM);
    // 5: RoPE apply
    const int n_rope = T_LEN * HQ * 64 + T_LEN * HKV * 64;
    rope_apply_kernel<<<n_rope / 256, 256>>>(Q, Kp);
    // 6: attention (tensor-core flash)
    attn_tc_kernel<<<dim3(T_LEN / 64, HQ), 128>>>(Q, Kp, Vp, Yp);
    // 7: output projection
    gemm_bf16x3<<<dim3(C_DIM / 128, T_LEN / 128), 256>>>(Yp, Wo, out, T_LEN, C_DIM, C_DIM);
}

// round 5
// speedup vs baseline: 9.2481x; 1.0573x over previous
#include <cuda_runtime.h>
#include <cuda_bf16.h>
#include <math.h>
#include <float.h>
#include <stdint.h>

// Problem constants
#define T_LEN   4096
#define C_DIM   2048
#define HQ      16
#define HKV     4
#define HD      128
#define WIN     1024

// Scratch (device globals; no allocations allowed)
__device__ float g_Q[T_LEN * HQ * HD];
__device__ float g_K[T_LEN * HKV * HD];
__device__ float g_V[T_LEN * HKV * HD];
__device__ float g_Y[T_LEN * HQ * HD];
__device__ float g_cos[T_LEN * 64];
__device__ float g_sin[T_LEN * 64];

// ---------------------------------------------------------------------------
// Common MMA helpers
// ---------------------------------------------------------------------------
#define LDMATRIX_X4(R0,R1,R2,R3,ADDR) \
    asm volatile("ldmatrix.sync.aligned.m8n8.x4.shared.b16 {%0,%1,%2,%3}, [%4];" \
        : "=r"(R0), "=r"(R1), "=r"(R2), "=r"(R3) : "r"(ADDR))

#define LDMATRIX_X4_T(R0,R1,R2,R3,ADDR) \
    asm volatile("ldmatrix.sync.aligned.m8n8.x4.trans.shared.b16 {%0,%1,%2,%3}, [%4];" \
        : "=r"(R0), "=r"(R1), "=r"(R2), "=r"(R3) : "r"(ADDR))

#define MMA_BF16(D, A0,A1,A2,A3, B0,B1) \
    asm volatile("mma.sync.aligned.m16n8k16.row.col.f32.bf16.bf16.f32 " \
        "{%0,%1,%2,%3}, {%4,%5,%6,%7}, {%8,%9}, {%0,%1,%2,%3};" \
        : "+f"((D)[0]), "+f"((D)[1]), "+f"((D)[2]), "+f"((D)[3]) \
        : "r"(A0), "r"(A1), "r"(A2), "r"(A3), "r"(B0), "r"(B1))

__device__ __forceinline__ uint32_t smem_u32(const void* p) {
    return (uint32_t)__cvta_generic_to_shared(p);
}

__device__ __forceinline__ void split2(float a, float b, uint32_t& hi, uint32_t& lo) {
    __nv_bfloat16 ah = __float2bfloat16_rn(a);
    __nv_bfloat16 bh = __float2bfloat16_rn(b);
    __nv_bfloat162 h(ah, bh);
    hi = *(uint32_t*)&h;
    __nv_bfloat162 l(__float2bfloat16_rn(a - __bfloat162float(ah)),
                     __float2bfloat16_rn(b - __bfloat162float(bh)));
    lo = *(uint32_t*)&l;
}

// ---------------------------------------------------------------------------
// bf16x3 split tensor-core GEMM, 128x128 tile, BK=32, 256 threads.
// 2-stage double-buffered dynamic smem + term-major MMA ordering.
// ---------------------------------------------------------------------------
#define A_STRIDE 40     // bf16 elems per A row (32 used)
#define B_STRIDE 136    // bf16 elems per B row (128 used)
#define A_TILE   (128 * A_STRIDE)          // 5120 elems
#define B_TILE   (32 * B_STRIDE)           // 4352 elems
#define AL_OFF   A_TILE                    // elem offsets within a stage
#define BH_OFF   (2 * A_TILE)
#define BL_OFF   (2 * A_TILE + B_TILE)
#define STAGE_ELEMS (2 * A_TILE + 2 * B_TILE)   // 18944
#define STAGE_BYTES (STAGE_ELEMS * 2)           // 37888
#define GEMM_SMEM   (2 * STAGE_BYTES)           // 75776

__global__ __launch_bounds__(256)
void gemm_bf16x3(const float* __restrict__ A, const float* __restrict__ B,
                 float* __restrict__ C, int M, int N, int K)
{
    extern __shared__ __nv_bfloat16 sm[];

    const int tid  = threadIdx.x;
    const int wid  = tid >> 5;
    const int lane = tid & 31;
    const int warp_m = wid & 3;
    const int warp_n = wid >> 2;
    const int bx = blockIdx.x, by = blockIdx.y;

    const int arow = tid >> 1;
    const int acol = (tid & 1) << 4;
    const int brow = tid >> 3;
    const int bcol = (tid & 7) << 4;

    const float* Ag = A + (size_t)(by * 128 + arow) * K + acol;
    const float* Bg = B + (size_t)brow * N + bx * 128 + bcol;

    float acc[2][8][4];
#pragma unroll
    for (int mi = 0; mi < 2; mi++)
#pragma unroll
        for (int nf = 0; nf < 8; nf++)
#pragma unroll
            for (int e = 0; e < 4; e++) acc[mi][nf][e] = 0.0f;

    // ldmatrix lane base addresses (stage 0)
    uint32_t a_base[2];
#pragma unroll
    for (int mi = 0; mi < 2; mi++) {
        int row = warp_m * 32 + mi * 16 + (lane & 15);
        a_base[mi] = smem_u32(sm) + (uint32_t)(row * A_STRIDE) * 2 + ((lane >> 4) << 4);
    }
    int b_row = (((lane >> 3) & 1) << 3) + (lane & 7);
    uint32_t b_base = smem_u32(sm) + (uint32_t)(BH_OFF + b_row * B_STRIDE + warp_n * 64) * 2
                      + ((lane >> 4) << 4);

    const uint32_t ALO = (uint32_t)AL_OFF * 2;          // bytes Ah -> Al
    const uint32_t BLO = (uint32_t)(BL_OFF - BH_OFF) * 2;  // bytes Bh -> Bl

    // Prologue: load tile 0, store to stage 0
    float4 pa[4], pb[4];
#pragma unroll
    for (int i = 0; i < 4; i++) {
        pa[i] = *(const float4*)(Ag + i * 4);
        pb[i] = *(const float4*)(Bg + i * 4);
    }
    {
        __nv_bfloat16* st = sm;
#pragma unroll
        for (int i = 0; i < 4; i++) {
            int offA = arow * A_STRIDE + acol + i * 4;
            uint32_t h0, l0, h1, l1;
            split2(pa[i].x, pa[i].y, h0, l0);
            split2(pa[i].z, pa[i].w, h1, l1);
            *(uint32_t*)&st[offA]              = h0;
            *(uint32_t*)&st[offA + 2]          = h1;
            *(uint32_t*)&st[AL_OFF + offA]     = l0;
            *(uint32_t*)&st[AL_OFF + offA + 2] = l1;
            int offB = brow * B_STRIDE + bcol + i * 4;
            split2(pb[i].x, pb[i].y, h0, l0);
            split2(pb[i].z, pb[i].w, h1, l1);
            *(uint32_t*)&st[BH_OFF + offB]     = h0;
            *(uint32_t*)&st[BH_OFF + offB + 2] = h1;
            *(uint32_t*)&st[BL_OFF + offB]     = l0;
            *(uint32_t*)&st[BL_OFF + offB + 2] = l1;
        }
    }
    __syncthreads();

    int s = 0;
    for (int k0 = 0; k0 < K; k0 += 32) {
        const bool more = (k0 + 32) < K;
        if (more) {
#pragma unroll
            for (int i = 0; i < 4; i++) {
                pa[i] = *(const float4*)(Ag + k0 + 32 + i * 4);
                pb[i] = *(const float4*)(Bg + (size_t)(k0 + 32) * N + i * 4);
            }
        }

        const uint32_t sb = (uint32_t)(s * STAGE_BYTES);
#pragma unroll
        for (int ks = 0; ks < 2; ks++) {
            uint32_t ahi[2][4], alo[2][4];
#pragma unroll
            for (int mi = 0; mi < 2; mi++) {
                uint32_t ad = a_base[mi] + sb + ks * 32;
                LDMATRIX_X4(ahi[mi][0], ahi[mi][1], ahi[mi][2], ahi[mi][3], ad);
                LDMATRIX_X4(alo[mi][0], alo[mi][1], alo[mi][2], alo[mi][3], ad + ALO);
            }
            uint32_t bhi[4][4], blo[4][4];
#pragma unroll
            for (int ng = 0; ng < 4; ng++) {
                uint32_t bd = b_base + sb + (uint32_t)(ks * 16 * B_STRIDE + ng * 16) * 2;
                LDMATRIX_X4_T(bhi[ng][0], bhi[ng][1], bhi[ng][2], bhi[ng][3], bd);
                LDMATRIX_X4_T(blo[ng][0], blo[ng][1], blo[ng][2], blo[ng][3], bd + BLO);
            }
            // term 1: hi*hi — 16 independent accumulators
#pragma unroll
            for (int mi = 0; mi < 2; mi++)
#pragma unroll
                for (int ng = 0; ng < 4; ng++) {
                    MMA_BF16(acc[mi][2*ng],   ahi[mi][0], ahi[mi][1], ahi[mi][2], ahi[mi][3], bhi[ng][0], bhi[ng][1]);
                    MMA_BF16(acc[mi][2*ng+1], ahi[mi][0], ahi[mi][1], ahi[mi][2], ahi[mi][3], bhi[ng][2], bhi[ng][3]);
                }
            // term 2: hi*lo
#pragma unroll
            for (int mi = 0; mi < 2; mi++)
#pragma unroll
                for (int ng = 0; ng < 4; ng++) {
                    MMA_BF16(acc[mi][2*ng],   ahi[mi][0], ahi[mi][1], ahi[mi][2], ahi[mi][3], blo[ng][0], blo[ng][1]);
                    MMA_BF16(acc[mi][2*ng+1], ahi[mi][0], ahi[mi][1], ahi[mi][2], ahi[mi][3], blo[ng][2], blo[ng][3]);
                }
            // term 3: lo*hi
#pragma unroll
            for (int mi = 0; mi < 2; mi++)
#pragma unroll
                for (int ng = 0; ng < 4; ng++) {
                    MMA_BF16(acc[mi][2*ng],   alo[mi][0], alo[mi][1], alo[mi][2], alo[mi][3], bhi[ng][0], bhi[ng][1]);
                    MMA_BF16(acc[mi][2*ng+1], alo[mi][0], alo[mi][1], alo[mi][2], alo[mi][3], bhi[ng][2], bhi[ng][3]);
                }
        }

        if (more) {
            __nv_bfloat16* st = sm + (s ^ 1) * STAGE_ELEMS;
#pragma unroll
            for (int i = 0; i < 4; i++) {
                int offA = arow * A_STRIDE + acol + i * 4;
                uint32_t h0, l0, h1, l1;
                split2(pa[i].x, pa[i].y, h0, l0);
                split2(pa[i].z, pa[i].w, h1, l1);
                *(uint32_t*)&st[offA]              = h0;
                *(uint32_t*)&st[offA + 2]          = h1;
                *(uint32_t*)&st[AL_OFF + offA]     = l0;
                *(uint32_t*)&st[AL_OFF + offA + 2] = l1;
                int offB = brow * B_STRIDE + bcol + i * 4;
                split2(pb[i].x, pb[i].y, h0, l0);
                split2(pb[i].z, pb[i].w, h1, l1);
                *(uint32_t*)&st[BH_OFF + offB]     = h0;
                *(uint32_t*)&st[BH_OFF + offB + 2] = h1;
                *(uint32_t*)&st[BL_OFF + offB]     = l0;
                *(uint32_t*)&st[BL_OFF + offB + 2] = l1;
            }
        }
        __syncthreads();
        s ^= 1;
    }

    const int trow = lane >> 2;
    const int tcol = (lane & 3) << 1;
#pragma unroll
    for (int mi = 0; mi < 2; mi++) {
#pragma unroll
        for (int nf = 0; nf < 8; nf++) {
            int rg = by * 128 + warp_m * 32 + mi * 16 + trow;
            int cg = bx * 128 + warp_n * 64 + nf * 8 + tcol;
            *(float2*)&C[(size_t)rg * N + cg]       = make_float2(acc[mi][nf][0], acc[mi][nf][1]);
            *(float2*)&C[(size_t)(rg + 8) * N + cg] = make_float2(acc[mi][nf][2], acc[mi][nf][3]);
        }
    }
}

// ---------------------------------------------------------------------------
// RoPE
// ---------------------------------------------------------------------------
__global__ void rope_table_kernel()
{
    int idx = blockIdx.x * blockDim.x + threadIdx.x;
    if (idx >= T_LEN * 64) return;
    int t = idx >> 6;
    int j = idx & 63;
    double e = exp(-(double)j * (log(10000.0) / 64.0));
    float invf = (float)e;
    float ang = (float)t * invf;
    double a = (double)ang;
    g_cos[idx] = (float)cos(a);
    g_sin[idx] = (float)sin(a);
}

__global__ void rope_apply_kernel(float* __restrict__ Q, float* __restrict__ K)
{
    const int NQ = T_LEN * HQ * 64;
    int idx = blockIdx.x * blockDim.x + threadIdx.x;
    float* p;
    int t, j;
    if (idx < NQ) {
        t = idx >> 10;
        int rem = idx & 1023;
        int h = rem >> 6;
        j = rem & 63;
        p = Q + (size_t)t * (HQ * HD) + h * HD;
    } else {
        int i2 = idx - NQ;
        t = i2 >> 8;
        int rem = i2 & 255;
        int h = rem >> 6;
        j = rem & 63;
        p = K + (size_t)t * (HKV * HD) + h * HD;
    }
    float cv = g_cos[t * 64 + j];
    float sv = g_sin[t * 64 + j];
    float x0 = p[j];
    float x1 = p[j + 64];
    p[j]      = x0 * cv - x1 * sv;
    p[j + 64] = x1 * cv + x0 * sv;
}

// ---------------------------------------------------------------------------
// Tensor-core flash attention with sliding window (bf16x3, term-major MMAs).
// Grid: (T/64, HQ). Block: 128 threads.
// ---------------------------------------------------------------------------
#define KVS 136

__global__ __launch_bounds__(128)
void attn_tc_kernel(const float* __restrict__ Q, const float* __restrict__ K,
                    const float* __restrict__ V, float* __restrict__ Y)
{
    __shared__ __nv_bfloat16 Kh[32][KVS];
    __shared__ __nv_bfloat16 Kl[32][KVS];
    __shared__ __nv_bfloat16 Vh[32][KVS];
    __shared__ __nv_bfloat16 Vl[32][KVS];

    const int qb  = blockIdx.x;
    const int h   = blockIdx.y;
    const int kvh = h >> 2;
    const int tid  = threadIdx.x;
    const int wid  = tid >> 5;
    const int lane = tid & 31;
    const int trow = lane >> 2;
    const int tc2  = (lane & 3) << 1;
    const int qrow0 = qb * 64 + wid * 16;

    uint32_t qhi[8][4], qlo[8][4];
#pragma unroll
    for (int ks = 0; ks < 8; ks++) {
#pragma unroll
        for (int r = 0; r < 4; r++) {
            int row = qrow0 + trow + ((r & 1) << 3);
            int d = ks * 16 + ((r >> 1) << 3) + tc2;
            float2 v = *(const float2*)(Q + (size_t)row * (HQ * HD) + h * HD + d);
            split2(v.x, v.y, qhi[ks][r], qlo[ks][r]);
        }
    }

    float oacc[16][4];
#pragma unroll
    for (int nf = 0; nf < 16; nf++)
#pragma unroll
        for (int e = 0; e < 4; e++) oacc[nf][e] = 0.0f;
    float m2[2]   = { -1e30f, -1e30f };
    float lsum[2] = { 0.0f, 0.0f };

    int jmin = qb * 64 - (WIN - 1);
    if (jmin < 0) jmin = 0;
    const int kb0 = jmin >> 5;
    const int kb1 = (qb * 64 + 63) >> 5;

    const int krow    = (lane & 7) + ((lane >> 4) << 3);
    const int kcoloff = ((lane >> 3) & 1) << 3;
    const int vrow    = (lane & 7) + (((lane >> 3) & 1) << 3);
    const int vcoloff = (lane >> 4) << 3;

    const uint32_t kh_base = smem_u32(Kh) + (uint32_t)(krow * KVS + kcoloff) * 2;
    const uint32_t kl_base = smem_u32(Kl) + (uint32_t)(krow * KVS + kcoloff) * 2;
    const uint32_t vh_base = smem_u32(Vh) + (uint32_t)(vrow * KVS + vcoloff) * 2;
    const uint32_t vl_base = smem_u32(Vl) + (uint32_t)(vrow * KVS + vcoloff) * 2;
    const uint32_t KROW16 = (uint32_t)(16 * KVS) * 2;

    const float SC = (float)(0.08838834764831845 * 1.4426950408889634);

    for (int kb = kb0; kb <= kb1; kb++) {
        const int jb = kb * 32;
        __syncthreads();
#pragma unroll
        for (int i = 0; i < 8; i++) {
            int f4  = tid + 128 * i;
            int row = f4 >> 5;
            int c4  = (f4 & 31) << 2;
            size_t g = (size_t)(jb + row) * (HKV * HD) + kvh * HD + c4;
            float4 kx = *(const float4*)(K + g);
            uint32_t h0, l0, h1, l1;
            split2(kx.x, kx.y, h0, l0);
            split2(kx.z, kx.w, h1, l1);
            *(uint32_t*)&Kh[row][c4]     = h0;
            *(uint32_t*)&Kh[row][c4 + 2] = h1;
            *(uint32_t*)&Kl[row][c4]     = l0;
            *(uint32_t*)&Kl[row][c4 + 2] = l1;
            float4 vx = *(const float4*)(V + g);
            split2(vx.x, vx.y, h0, l0);
            split2(vx.z, vx.w, h1, l1);
            *(uint32_t*)&Vh[row][c4]     = h0;
            *(uint32_t*)&Vh[row][c4 + 2] = h1;
            *(uint32_t*)&Vl[row][c4]     = l0;
            *(uint32_t*)&Vl[row][c4 + 2] = l1;
        }
        __syncthreads();

        float sacc[4][4];
#pragma unroll
        for (int f = 0; f < 4; f++)
#pragma unroll
            for (int e = 0; e < 4; e++) sacc[f][e] = 0.0f;

#pragma unroll
        for (int ks = 0; ks < 8; ks++) {
            uint32_t off = (uint32_t)(ks * 16) * 2;
            uint32_t bh0[4], bh1[4], bl0[4], bl1[4];
            LDMATRIX_X4(bh0[0], bh0[1], bh0[2], bh0[3], kh_base + off);
            LDMATRIX_X4(bh1[0], bh1[1], bh1[2], bh1[3], kh_base + off + KROW16);
            LDMATRIX_X4(bl0[0], bl0[1], bl0[2], bl0[3], kl_base + off);
            LDMATRIX_X4(bl1[0], bl1[1], bl1[2], bl1[3], kl_base + off + KROW16);
            // term-major: 4 independent sacc per term
            MMA_BF16(sacc[0], qhi[ks][0], qhi[ks][1], qhi[ks][2], qhi[ks][3], bh0[0], bh0[1]);
            MMA_BF16(sacc[1], qhi[ks][0], qhi[ks][1], qhi[ks][2], qhi[ks][3], bh0[2], bh0[3]);
            MMA_BF16(sacc[2], qhi[ks][0], qhi[ks][1], qhi[ks][2], qhi[ks][3], bh1[0], bh1[1]);
            MMA_BF16(sacc[3], qhi[ks][0], qhi[ks][1], qhi[ks][2], qhi[ks][3], bh1[2], bh1[3]);
            MMA_BF16(sacc[0], qlo[ks][0], qlo[ks][1], qlo[ks][2], qlo[ks][3], bh0[0], bh0[1]);
            MMA_BF16(sacc[1], qlo[ks][0], qlo[ks][1], qlo[ks][2], qlo[ks][3], bh0[2], bh0[3]);
            MMA_BF16(sacc[2], qlo[ks][0], qlo[ks][1], qlo[ks][2], qlo[ks][3], bh1[0], bh1[1]);
            MMA_BF16(sacc[3], qlo[ks][0], qlo[ks][1], qlo[ks][2], qlo[ks][3], bh1[2], bh1[3]);
            MMA_BF16(sacc[0], qhi[ks][0], qhi[ks][1], qhi[ks][2], qhi[ks][3], bl0[0], bl0[1]);
            MMA_BF16(sacc[1], qhi[ks][0], qhi[ks][1], qhi[ks][2], qhi[ks][3], bl0[2], bl0[3]);
            MMA_BF16(sacc[2], qhi[ks][0], qhi[ks][1], qhi[ks][2], qhi[ks][3], bl1[0], bl1[1]);
            MMA_BF16(sacc[3], qhi[ks][0], qhi[ks][1], qhi[ks][2], qhi[ks][3], bl1[2], bl1[3]);
        }

        // masked online softmax (branchless, base-2)
        float bm0 = -1e30f, bm1 = -1e30f;
#pragma unroll
        for (int f = 0; f < 4; f++) {
            int j0 = jb + f * 8 + tc2;
#pragma unroll
            for (int e = 0; e < 4; e++) {
                int j  = j0 + (e & 1);
                int qi = qrow0 + trow + ((e >> 1) << 3);
                bool ok = (j <= qi) && ((qi - j) < WIN);
                float sx = ok ? sacc[f][e] * SC : -1e30f;
                sacc[f][e] = sx;
                if (e < 2) bm0 = fmaxf(bm0, sx); else bm1 = fmaxf(bm1, sx);
            }
        }
        bm0 = fmaxf(bm0, __shfl_xor_sync(0xffffffffu, bm0, 1));
        bm0 = fmaxf(bm0, __shfl_xor_sync(0xffffffffu, bm0, 2));
        bm1 = fmaxf(bm1, __shfl_xor_sync(0xffffffffu, bm1, 1));
        bm1 = fmaxf(bm1, __shfl_xor_sync(0xffffffffu, bm1, 2));

        float mn0 = fmaxf(m2[0], bm0);
        float mn1 = fmaxf(m2[1], bm1);
        float mm0 = fmaxf(mn0, -1e20f);
        float mm1 = fmaxf(mn1, -1e20f);
        float f0 = exp2f(m2[0] - mm0);
        float f1 = exp2f(m2[1] - mm1);
        m2[0] = mn0; m2[1] = mn1;

        float ps0 = 0.0f, ps1 = 0.0f;
#pragma unroll
        for (int f = 0; f < 4; f++) {
            sacc[f][0] = exp2f(sacc[f][0] - mm0);
            sacc[f][1] = exp2f(sacc[f][1] - mm0);
            sacc[f][2] = exp2f(sacc[f][2] - mm1);
            sacc[f][3] = exp2f(sacc[f][3] - mm1);
            ps0 += sacc[f][0] + sacc[f][1];
            ps1 += sacc[f][2] + sacc[f][3];
        }
        ps0 += __shfl_xor_sync(0xffffffffu, ps0, 1);
        ps0 += __shfl_xor_sync(0xffffffffu, ps0, 2);
        ps1 += __shfl_xor_sync(0xffffffffu, ps1, 1);
        ps1 += __shfl_xor_sync(0xffffffffu, ps1, 2);
        lsum[0] = lsum[0] * f0 + ps0;
        lsum[1] = lsum[1] * f1 + ps1;

#pragma unroll
        for (int nf = 0; nf < 16; nf++) {
            oacc[nf][0] *= f0; oacc[nf][1] *= f0;
            oacc[nf][2] *= f1; oacc[nf][3] *= f1;
        }

        uint32_t phi[2][4], plo[2][4];
#pragma unroll
        for (int kp = 0; kp < 2; kp++) {
            split2(sacc[2*kp][0],   sacc[2*kp][1],   phi[kp][0], plo[kp][0]);
            split2(sacc[2*kp][2],   sacc[2*kp][3],   phi[kp][1], plo[kp][1]);
            split2(sacc[2*kp+1][0], sacc[2*kp+1][1], phi[kp][2], plo[kp][2]);
            split2(sacc[2*kp+1][2], sacc[2*kp+1][3], phi[kp][3], plo[kp][3]);
        }

#pragma unroll
        for (int kp = 0; kp < 2; kp++) {
            uint32_t rowoff = (uint32_t)(kp * 16 * KVS) * 2;
#pragma unroll
            for (int ng = 0; ng < 8; ng++) {
                uint32_t coff = rowoff + (uint32_t)(ng * 16) * 2;
                uint32_t vh4[4], vl4[4];
                LDMATRIX_X4_T(vh4[0], vh4[1], vh4[2], vh4[3], vh_base + coff);
                LDMATRIX_X4_T(vl4[0], vl4[1], vl4[2], vl4[3], vl_base + coff);
                // interleave: alternate accumulators between dependent MMAs
                MMA_BF16(oacc[2*ng],   phi[kp][0], phi[kp][1], phi[kp][2], phi[kp][3], vh4[0], vh4[1]);
                MMA_BF16(oacc[2*ng+1], phi[kp][0], phi[kp][1], phi[kp][2], phi[kp][3], vh4[2], vh4[3]);
                MMA_BF16(oacc[2*ng],   plo[kp][0], plo[kp][1], plo[kp][2], plo[kp][3], vh4[0], vh4[1]);
                MMA_BF16(oacc[2*ng+1], plo[kp][0], plo[kp][1], plo[kp][2], plo[kp][3], vh4[2], vh4[3]);
                MMA_BF16(oacc[2*ng],   phi[kp][0], phi[kp][1], phi[kp][2], phi[kp][3], vl4[0], vl4[1]);
                MMA_BF16(oacc[2*ng+1], phi[kp][0], phi[kp][1], phi[kp][2], phi[kp][3], vl4[2], vl4[3]);
            }
        }
    }

    float il0 = 1.0f / lsum[0];
    float il1 = 1.0f / lsum[1];
    const int row0 = qrow0 + trow;
#pragma unroll
    for (int nf = 0; nf < 16; nf++) {
        int col = h * HD + nf * 8 + tc2;
        *(float2*)&Y[(size_t)row0 * (HQ * HD) + col] =
            make_float2(oacc[nf][0] * il0, oacc[nf][1] * il0);
        *(float2*)&Y[(size_t)(row0 + 8) * (HQ * HD) + col] =
            make_float2(oacc[nf][2] * il1, oacc[nf][3] * il1);
    }
}

// ---------------------------------------------------------------------------
// Launch
// ---------------------------------------------------------------------------
extern "C" void kernel_launch(void* const* d_in, const int* in_sizes, int n_in,
                              void* d_out, int out_size)
{
    const float* x  = (const float*)d_in[0];
    const float* Wq = (const float*)d_in[1];
    const float* Wk = (const float*)d_in[2];
    const float* Wv = (const float*)d_in[3];
    const float* Wo = (const float*)d_in[4];
    float* out = (float*)d_out;

    float *Q, *Kp, *Vp, *Yp;
    cudaGetSymbolAddress((void**)&Q,  g_Q);
    cudaGetSymbolAddress((void**)&Kp, g_K);
    cudaGetSymbolAddress((void**)&Vp, g_V);
    cudaGetSymbolAddress((void**)&Yp, g_Y);

    static bool attr_done = false;
    if (!attr_done) {
        cudaFuncSetAttribute(gemm_bf16x3, cudaFuncAttributeMaxDynamicSharedMemorySize, GEMM_SMEM);
        attr_done = true;
    }

    // 1: RoPE table
    rope_table_kernel<<<(T_LEN * 64 + 255) / 256, 256>>>();
    // 2,3: K,V projections
    gemm_bf16x3<<<dim3((HKV * HD) / 128, T_LEN / 128), 256, GEMM_SMEM>>>(x, Wk, Kp, T_LEN, HKV * HD, C_DIM);
    gemm_bf16x3<<<dim3((HKV * HD) / 128, T_LEN / 128), 256, GEMM_SMEM>>>(x, Wv, Vp, T_LEN, HKV * HD, C_DIM);
    // 4: Q projection (ncu capture slot)
    gemm_bf16x3<<<dim3((HQ * HD) / 128, T_LEN / 128), 256, GEMM_SMEM>>>(x, Wq, Q, T_LEN, HQ * HD, C_DIM);
    // 5: RoPE apply
    const int n_rope = T_LEN * HQ * 64 + T_LEN * HKV * 64;
    rope_apply_kernel<<<n_rope / 256, 256>>>(Q, Kp);
    // 6: attention
    attn_tc_kernel<<<dim3(T_LEN / 64, HQ), 128>>>(Q, Kp, Vp, Yp);
    // 7: output projection
    gemm_bf16x3<<<dim3(C_DIM / 128, T_LEN / 128), 256, GEMM_SMEM>>>(Yp, Wo, out, T_LEN, C_DIM, C_DIM);
}

// round 7
// speedup vs baseline: 11.8055x; 1.2765x over previous
#include <cuda_runtime.h>
#include <cuda_bf16.h>
#include <math.h>
#include <float.h>
#include <stdint.h>

// Problem constants
#define T_LEN   4096
#define C_DIM   2048
#define HQ      16
#define HKV     4
#define HD      128
#define WIN     1024
#define NKV     (HKV * HD)     // 512

// fp32 scratch
__device__ float g_Q[T_LEN * HQ * HD];
__device__ float g_K[T_LEN * NKV];
__device__ float g_V[T_LEN * NKV];
__device__ float g_cos[T_LEN * 64];
__device__ float g_sin[T_LEN * 64];

// bf16 split operands
__device__ __nv_bfloat16 g_xh[T_LEN * C_DIM],  g_xl[T_LEN * C_DIM];
__device__ __nv_bfloat16 g_yh[T_LEN * C_DIM],  g_yl[T_LEN * C_DIM];
__device__ __nv_bfloat16 g_wqt_h[C_DIM * C_DIM], g_wqt_l[C_DIM * C_DIM];
__device__ __nv_bfloat16 g_wkt_h[NKV * C_DIM],   g_wkt_l[NKV * C_DIM];
__device__ __nv_bfloat16 g_wvt_h[NKV * C_DIM],   g_wvt_l[NKV * C_DIM];
__device__ __nv_bfloat16 g_wot_h[C_DIM * C_DIM], g_wot_l[C_DIM * C_DIM];

// ---------------------------------------------------------------------------
// helpers
// ---------------------------------------------------------------------------
__device__ __forceinline__ uint32_t smem_u32(const void* p) {
    return (uint32_t)__cvta_generic_to_shared(p);
}

__device__ __forceinline__ void split2(float a, float b, uint32_t& hi, uint32_t& lo) {
    __nv_bfloat16 ah = __float2bfloat16_rn(a);
    __nv_bfloat16 bh = __float2bfloat16_rn(b);
    __nv_bfloat162 h(ah, bh);
    hi = *(uint32_t*)&h;
    __nv_bfloat162 l(__float2bfloat16_rn(a - __bfloat162float(ah)),
                     __float2bfloat16_rn(b - __bfloat162float(bh)));
    lo = *(uint32_t*)&l;
}

#define LDMATRIX_X4(R0,R1,R2,R3,ADDR) \
    asm volatile("ldmatrix.sync.aligned.m8n8.x4.shared.b16 {%0,%1,%2,%3}, [%4];" \
        : "=r"(R0), "=r"(R1), "=r"(R2), "=r"(R3) : "r"(ADDR))

#define LDMATRIX_X4_T(R0,R1,R2,R3,ADDR) \
    asm volatile("ldmatrix.sync.aligned.m8n8.x4.trans.shared.b16 {%0,%1,%2,%3}, [%4];" \
        : "=r"(R0), "=r"(R1), "=r"(R2), "=r"(R3) : "r"(ADDR))

#define MMA_BF16(D, A0,A1,A2,A3, B0,B1) \
    asm volatile("mma.sync.aligned.m16n8k16.row.col.f32.bf16.bf16.f32 " \
        "{%0,%1,%2,%3}, {%4,%5,%6,%7}, {%8,%9}, {%0,%1,%2,%3};" \
        : "+f"((D)[0]), "+f"((D)[1]), "+f"((D)[2]), "+f"((D)[3]) \
        : "r"(A0), "r"(A1), "r"(A2), "r"(A3), "r"(B0), "r"(B1))

__device__ __forceinline__ void cp_async16(uint32_t dst, const void* src) {
    asm volatile("cp.async.cg.shared.global [%0], [%1], 16;" :: "r"(dst), "l"(src));
}
__device__ __forceinline__ void cp_commit() {
    asm volatile("cp.async.commit_group;" ::: "memory");
}
template <int NN> __device__ __forceinline__ void cp_wait() {
    asm volatile("cp.async.wait_group %0;" :: "n"(NN) : "memory");
}

// ---------------------------------------------------------------------------
// Prep kernels
// ---------------------------------------------------------------------------
__global__ void split_f32_kernel(const float* __restrict__ src,
                                 __nv_bfloat16* __restrict__ hi,
                                 __nv_bfloat16* __restrict__ lo, int n4)
{
    int i = blockIdx.x * blockDim.x + threadIdx.x;
    if (i >= n4) return;
    float4 v = ((const float4*)src)[i];
    uint32_t h0, l0, h1, l1;
    split2(v.x, v.y, h0, l0);
    split2(v.z, v.w, h1, l1);
    ((uint2*)hi)[i] = make_uint2(h0, h1);
    ((uint2*)lo)[i] = make_uint2(l0, l1);
}

// W [K, N] fp32 -> Wt_hi/lo [N, K] bf16
__global__ void transpose_split_kernel(const float* __restrict__ W,
                                       __nv_bfloat16* __restrict__ Th,
                                       __nv_bfloat16* __restrict__ Tl,
                                       int Kd, int Nd)
{
    __shared__ float tile[32][33];
    const int bx = blockIdx.x;
    const int by = blockIdx.y;
    const int x = threadIdx.x;
    const int y = threadIdx.y;
#pragma unroll
    for (int j = 0; j < 32; j += 8)
        tile[y + j][x] = W[(size_t)(by * 32 + y + j) * Nd + bx * 32 + x];
    __syncthreads();
#pragma unroll
    for (int j = 0; j < 32; j += 8) {
        float v = tile[x][y + j];
        __nv_bfloat16 h = __float2bfloat16_rn(v);
        size_t o = (size_t)(bx * 32 + y + j) * Kd + by * 32 + x;
        Th[o] = h;
        Tl[o] = __float2bfloat16_rn(v - __bfloat162float(h));
    }
}

// ---------------------------------------------------------------------------
// bf16x3 GEMM on pre-split operands: C[M,N] = A[M,K] * B[N,K]^T (fp32 out).
// 128x128 block, BK=64, 4 warps (warp tile 64x64), 3-stage cp.async pipeline.
// Smem rows are 128B (=64 bf16) SW128-swizzled; A and B both non-trans LDSM.
// ---------------------------------------------------------------------------
#define G_AH 0
#define G_AL 16384
#define G_BH 32768
#define G_BL 49152
#define G_STAGE 65536
#define G_SMEM  (3 * G_STAGE)

__device__ __forceinline__ void g_load_stage(uint32_t dstbase,
    const __nv_bfloat16* __restrict__ Ah, const __nv_bfloat16* __restrict__ Al,
    const __nv_bfloat16* __restrict__ Bh, const __nv_bfloat16* __restrict__ Bl,
    int bm, int bn, int k0, int K, int tid)
{
    const int row = tid >> 3;          // 0..15
    const int c   = tid & 7;           // 16B granule
    const uint32_t swc = (uint32_t)((c ^ (row & 7)) << 4);
#pragma unroll
    for (int jj = 0; jj < 8; jj++) {
        int r = row + 16 * jj;
        uint32_t so = (uint32_t)r * 128 + swc;
        size_t ga = (size_t)(bm + r) * K + k0 + c * 8;
        size_t gb = (size_t)(bn + r) * K + k0 + c * 8;
        cp_async16(dstbase + G_AH + so, Ah + ga);
        cp_async16(dstbase + G_AL + so, Al + ga);
        cp_async16(dstbase + G_BH + so, Bh + gb);
        cp_async16(dstbase + G_BL + so, Bl + gb);
    }
}

__global__ __launch_bounds__(128)
void gemm_split(const __nv_bfloat16* __restrict__ Ah, const __nv_bfloat16* __restrict__ Al,
                const __nv_bfloat16* __restrict__ Bh, const __nv_bfloat16* __restrict__ Bl,
                float* __restrict__ C, int M, int N, int K)
{
    extern __shared__ char smg[];
    const int tid  = threadIdx.x;
    const int wid  = tid >> 5;
    const int lane = tid & 31;
    const int warp_m = wid & 1;
    const int warp_n = wid >> 1;
    const int bm = blockIdx.y * 128;
    const int bn = blockIdx.x * 128;
    const uint32_t sbase = smem_u32(smg);

    // lane addressing (non-trans ldmatrix for both A and B)
    const int ar  = (lane & 7) | (((lane >> 3) & 1) << 3);
    const int ag  = lane >> 4;
    const int ar7 = ar & 7;
    const int br  = (lane & 7) | ((lane >> 4) << 3);
    const int bg  = (lane >> 3) & 1;
    const int br7 = lane & 7;

    uint32_t a_ro[4], b_ro[4];
#pragma unroll
    for (int mi = 0; mi < 4; mi++)
        a_ro[mi] = (uint32_t)(warp_m * 64 + mi * 16 + ar) * 128 + G_AH;
#pragma unroll
    for (int ng = 0; ng < 4; ng++)
        b_ro[ng] = (uint32_t)(warp_n * 64 + ng * 16 + br) * 128 + G_BH;

    float acc[4][8][4];
#pragma unroll
    for (int mi = 0; mi < 4; mi++)
#pragma unroll
        for (int nf = 0; nf < 8; nf++)
#pragma unroll
            for (int e = 0; e < 4; e++) acc[mi][nf][e] = 0.0f;

    const int NK = K >> 6;

    g_load_stage(sbase, Ah, Al, Bh, Bl, bm, bn, 0, K, tid);
    cp_commit();
    g_load_stage(sbase + G_STAGE, Ah, Al, Bh, Bl, bm, bn, 64, K, tid);
    cp_commit();

    int sidx = 0, lidx = 2;
    for (int i = 0; i < NK; i++) {
        cp_wait<1>();
        __syncthreads();

        if (i + 2 < NK)
            g_load_stage(sbase + lidx * G_STAGE, Ah, Al, Bh, Bl, bm, bn, (i + 2) * 64, K, tid);
        cp_commit();
        lidx = (lidx == 2) ? 0 : lidx + 1;

        const uint32_t stb = sbase + sidx * G_STAGE;
        sidx = (sidx == 2) ? 0 : sidx + 1;

#pragma unroll
        for (int ks = 0; ks < 4; ks++) {
            const uint32_t cA = (uint32_t)(((ks * 2 + ag) ^ ar7) << 4);
            const uint32_t cB = (uint32_t)(((ks * 2 + bg) ^ br7) << 4);
            uint32_t ahi[4][4], alo[4][4];
#pragma unroll
            for (int mi = 0; mi < 4; mi++) {
                uint32_t ad = stb + a_ro[mi] + cA;
                LDMATRIX_X4(ahi[mi][0], ahi[mi][1], ahi[mi][2], ahi[mi][3], ad);
                LDMATRIX_X4(alo[mi][0], alo[mi][1], alo[mi][2], alo[mi][3], ad + 16384);
            }
            uint32_t bhi[4][4], blo[4][4];
#pragma unroll
            for (int ng = 0; ng < 4; ng++) {
                uint32_t bd = stb + b_ro[ng] + cB;
                LDMATRIX_X4(bhi[ng][0], bhi[ng][1], bhi[ng][2], bhi[ng][3], bd);
                LDMATRIX_X4(blo[ng][0], blo[ng][1], blo[ng][2], blo[ng][3], bd + 16384);
            }
            // term hi*hi
#pragma unroll
            for (int mi = 0; mi < 4; mi++)
#pragma unroll
                for (int ng = 0; ng < 4; ng++) {
                    MMA_BF16(acc[mi][2*ng],   ahi[mi][0], ahi[mi][1], ahi[mi][2], ahi[mi][3], bhi[ng][0], bhi[ng][1]);
                    MMA_BF16(acc[mi][2*ng+1], ahi[mi][0], ahi[mi][1], ahi[mi][2], ahi[mi][3], bhi[ng][2], bhi[ng][3]);
                }
            // term hi*lo
#pragma unroll
            for (int mi = 0; mi < 4; mi++)
#pragma unroll
                for (int ng = 0; ng < 4; ng++) {
                    MMA_BF16(acc[mi][2*ng],   ahi[mi][0], ahi[mi][1], ahi[mi][2], ahi[mi][3], blo[ng][0], blo[ng][1]);
                    MMA_BF16(acc[mi][2*ng+1], ahi[mi][0], ahi[mi][1], ahi[mi][2], ahi[mi][3], blo[ng][2], blo[ng][3]);
                }
            // term lo*hi
#pragma unroll
            for (int mi = 0; mi < 4; mi++)
#pragma unroll
                for (int ng = 0; ng < 4; ng++) {
                    MMA_BF16(acc[mi][2*ng],   alo[mi][0], alo[mi][1], alo[mi][2], alo[mi][3], bhi[ng][0], bhi[ng][1]);
                    MMA_BF16(acc[mi][2*ng+1], alo[mi][0], alo[mi][1], alo[mi][2], alo[mi][3], bhi[ng][2], bhi[ng][3]);
                }
        }
    }

    const int trow = lane >> 2;
    const int tcol = (lane & 3) << 1;
#pragma unroll
    for (int mi = 0; mi < 4; mi++) {
#pragma unroll
        for (int nf = 0; nf < 8; nf++) {
            int rg = bm + warp_m * 64 + mi * 16 + trow;
            int cg = bn + warp_n * 64 + nf * 8 + tcol;
            *(float2*)&C[(size_t)rg * N + cg]       = make_float2(acc[mi][nf][0], acc[mi][nf][1]);
            *(float2*)&C[(size_t)(rg + 8) * N + cg] = make_float2(acc[mi][nf][2], acc[mi][nf][3]);
        }
    }
}

// ---------------------------------------------------------------------------
// RoPE
// ---------------------------------------------------------------------------
__global__ void rope_table_kernel()
{
    int idx = blockIdx.x * blockDim.x + threadIdx.x;
    if (idx >= T_LEN * 64) return;
    int t = idx >> 6;
    int j = idx & 63;
    double e = exp(-(double)j * (log(10000.0) / 64.0));
    float invf = (float)e;
    float ang = (float)t * invf;
    double a = (double)ang;
    g_cos[idx] = (float)cos(a);
    g_sin[idx] = (float)sin(a);
}

__global__ void rope_apply_kernel(float* __restrict__ Q, float* __restrict__ K)
{
    const int NQ = T_LEN * HQ * 64;
    int idx = blockIdx.x * blockDim.x + threadIdx.x;
    float* p;
    int t, j;
    if (idx < NQ) {
        t = idx >> 10;
        int rem = idx & 1023;
        int h = rem >> 6;
        j = rem & 63;
        p = Q + (size_t)t * (HQ * HD) + h * HD;
    } else {
        int i2 = idx - NQ;
        t = i2 >> 8;
        int rem = i2 & 255;
        int h = rem >> 6;
        j = rem & 63;
        p = K + (size_t)t * NKV + h * HD;
    }
    float cv = g_cos[t * 64 + j];
    float sv = g_sin[t * 64 + j];
    float x0 = p[j];
    float x1 = p[j + 64];
    p[j]      = x0 * cv - x1 * sv;
    p[j + 64] = x1 * cv + x0 * sv;
}

// ---------------------------------------------------------------------------
// Tensor-core flash attention; epilogue writes pre-split bf16 Y (hi/lo).
// Grid: (T/64, HQ). Block: 128 threads.
// ---------------------------------------------------------------------------
#define KVS 136

__global__ __launch_bounds__(128)
void attn_tc_kernel(const float* __restrict__ Q, const float* __restrict__ K,
                    const float* __restrict__ V,
                    __nv_bfloat16* __restrict__ Yh, __nv_bfloat16* __restrict__ Yl)
{
    __shared__ __nv_bfloat16 Kh[32][KVS];
    __shared__ __nv_bfloat16 Kl[32][KVS];
    __shared__ __nv_bfloat16 Vh[32][KVS];
    __shared__ __nv_bfloat16 Vl[32][KVS];

    const int qb  = blockIdx.x;
    const int h   = blockIdx.y;
    const int kvh = h >> 2;
    const int tid  = threadIdx.x;
    const int wid  = tid >> 5;
    const int lane = tid & 31;
    const int trow = lane >> 2;
    const int tc2  = (lane & 3) << 1;
    const int qrow0 = qb * 64 + wid * 16;

    uint32_t qhi[8][4], qlo[8][4];
#pragma unroll
    for (int ks = 0; ks < 8; ks++) {
#pragma unroll
        for (int r = 0; r < 4; r++) {
            int row = qrow0 + trow + ((r & 1) << 3);
            int d = ks * 16 + ((r >> 1) << 3) + tc2;
            float2 v = *(const float2*)(Q + (size_t)row * (HQ * HD) + h * HD + d);
            split2(v.x, v.y, qhi[ks][r], qlo[ks][r]);
        }
    }

    float oacc[16][4];
#pragma unroll
    for (int nf = 0; nf < 16; nf++)
#pragma unroll
        for (int e = 0; e < 4; e++) oacc[nf][e] = 0.0f;
    float m2[2]   = { -1e30f, -1e30f };
    float lsum[2] = { 0.0f, 0.0f };

    int jmin = qb * 64 - (WIN - 1);
    if (jmin < 0) jmin = 0;
    const int kb0 = jmin >> 5;
    const int kb1 = (qb * 64 + 63) >> 5;

    const int krow    = (lane & 7) + ((lane >> 4) << 3);
    const int kcoloff = ((lane >> 3) & 1) << 3;
    const int vrow    = (lane & 7) + (((lane >> 3) & 1) << 3);
    const int vcoloff = (lane >> 4) << 3;

    const uint32_t kh_base = smem_u32(Kh) + (uint32_t)(krow * KVS + kcoloff) * 2;
    const uint32_t kl_base = smem_u32(Kl) + (uint32_t)(krow * KVS + kcoloff) * 2;
    const uint32_t vh_base = smem_u32(Vh) + (uint32_t)(vrow * KVS + vcoloff) * 2;
    const uint32_t vl_base = smem_u32(Vl) + (uint32_t)(vrow * KVS + vcoloff) * 2;
    const uint32_t KROW16 = (uint32_t)(16 * KVS) * 2;

    const float SC = (float)(0.08838834764831845 * 1.4426950408889634);

    for (int kb = kb0; kb <= kb1; kb++) {
        const int jb = kb * 32;
        __syncthreads();
#pragma unroll
        for (int i = 0; i < 8; i++) {
            int f4  = tid + 128 * i;
            int row = f4 >> 5;
            int c4  = (f4 & 31) << 2;
            size_t g = (size_t)(jb + row) * NKV + kvh * HD + c4;
            float4 kx = *(const float4*)(K + g);
            uint32_t h0, l0, h1, l1;
            split2(kx.x, kx.y, h0, l0);
            split2(kx.z, kx.w, h1, l1);
            *(uint32_t*)&Kh[row][c4]     = h0;
            *(uint32_t*)&Kh[row][c4 + 2] = h1;
            *(uint32_t*)&Kl[row][c4]     = l0;
            *(uint32_t*)&Kl[row][c4 + 2] = l1;
            float4 vx = *(const float4*)(V + g);
            split2(vx.x, vx.y, h0, l0);
            split2(vx.z, vx.w, h1, l1);
            *(uint32_t*)&Vh[row][c4]     = h0;
            *(uint32_t*)&Vh[row][c4 + 2] = h1;
            *(uint32_t*)&Vl[row][c4]     = l0;
            *(uint32_t*)&Vl[row][c4 + 2] = l1;
        }
        __syncthreads();

        float sacc[4][4];
#pragma unroll
        for (int f = 0; f < 4; f++)
#pragma unroll
            for (int e = 0; e < 4; e++) sacc[f][e] = 0.0f;

#pragma unroll
        for (int ks = 0; ks < 8; ks++) {
            uint32_t off = (uint32_t)(ks * 16) * 2;
            uint32_t bh0[4], bh1[4], bl0[4], bl1[4];
            LDMATRIX_X4(bh0[0], bh0[1], bh0[2], bh0[3], kh_base + off);
            LDMATRIX_X4(bh1[0], bh1[1], bh1[2], bh1[3], kh_base + off + KROW16);
            LDMATRIX_X4(bl0[0], bl0[1], bl0[2], bl0[3], kl_base + off);
            LDMATRIX_X4(bl1[0], bl1[1], bl1[2], bl1[3], kl_base + off + KROW16);
            MMA_BF16(sacc[0], qhi[ks][0], qhi[ks][1], qhi[ks][2], qhi[ks][3], bh0[0], bh0[1]);
            MMA_BF16(sacc[1], qhi[ks][0], qhi[ks][1], qhi[ks][2], qhi[ks][3], bh0[2], bh0[3]);
            MMA_BF16(sacc[2], qhi[ks][0], qhi[ks][1], qhi[ks][2], qhi[ks][3], bh1[0], bh1[1]);
            MMA_BF16(sacc[3], qhi[ks][0], qhi[ks][1], qhi[ks][2], qhi[ks][3], bh1[2], bh1[3]);
            MMA_BF16(sacc[0], qlo[ks][0], qlo[ks][1], qlo[ks][2], qlo[ks][3], bh0[0], bh0[1]);
            MMA_BF16(sacc[1], qlo[ks][0], qlo[ks][1], qlo[ks][2], qlo[ks][3], bh0[2], bh0[3]);
            MMA_BF16(sacc[2], qlo[ks][0], qlo[ks][1], qlo[ks][2], qlo[ks][3], bh1[0], bh1[1]);
            MMA_BF16(sacc[3], qlo[ks][0], qlo[ks][1], qlo[ks][2], qlo[ks][3], bh1[2], bh1[3]);
            MMA_BF16(sacc[0], qhi[ks][0], qhi[ks][1], qhi[ks][2], qhi[ks][3], bl0[0], bl0[1]);
            MMA_BF16(sacc[1], qhi[ks][0], qhi[ks][1], qhi[ks][2], qhi[ks][3], bl0[2], bl0[3]);
            MMA_BF16(sacc[2], qhi[ks][0], qhi[ks][1], qhi[ks][2], qhi[ks][3], bl1[0], bl1[1]);
            MMA_BF16(sacc[3], qhi[ks][0], qhi[ks][1], qhi[ks][2], qhi[ks][3], bl1[2], bl1[3]);
        }

        float bm0 = -1e30f, bm1 = -1e30f;
#pragma unroll
        for (int f = 0; f < 4; f++) {
            int j0 = jb + f * 8 + tc2;
#pragma unroll
            for (int e = 0; e < 4; e++) {
                int j  = j0 + (e & 1);
                int qi = qrow0 + trow + ((e >> 1) << 3);
                bool ok = (j <= qi) && ((qi - j) < WIN);
                float sx = ok ? sacc[f][e] * SC : -1e30f;
                sacc[f][e] = sx;
                if (e < 2) bm0 = fmaxf(bm0, sx); else bm1 = fmaxf(bm1, sx);
            }
        }
        bm0 = fmaxf(bm0, __shfl_xor_sync(0xffffffffu, bm0, 1));
        bm0 = fmaxf(bm0, __shfl_xor_sync(0xffffffffu, bm0, 2));
        bm1 = fmaxf(bm1, __shfl_xor_sync(0xffffffffu, bm1, 1));
        bm1 = fmaxf(bm1, __shfl_xor_sync(0xffffffffu, bm1, 2));

        float mn0 = fmaxf(m2[0], bm0);
        float mn1 = fmaxf(m2[1], bm1);
        float mm0 = fmaxf(mn0, -1e20f);
        float mm1 = fmaxf(mn1, -1e20f);
        float f0 = exp2f(m2[0] - mm0);
        float f1 = exp2f(m2[1] - mm1);
        m2[0] = mn0; m2[1] = mn1;

        float ps0 = 0.0f, ps1 = 0.0f;
#pragma unroll
        for (int f = 0; f < 4; f++) {
            sacc[f][0] = exp2f(sacc[f][0] - mm0);
            sacc[f][1] = exp2f(sacc[f][1] - mm0);
            sacc[f][2] = exp2f(sacc[f][2] - mm1);
            sacc[f][3] = exp2f(sacc[f][3] - mm1);
            ps0 += sacc[f][0] + sacc[f][1];
            ps1 += sacc[f][2] + sacc[f][3];
        }
        ps0 += __shfl_xor_sync(0xffffffffu, ps0, 1);
        ps0 += __shfl_xor_sync(0xffffffffu, ps0, 2);
        ps1 += __shfl_xor_sync(0xffffffffu, ps1, 1);
        ps1 += __shfl_xor_sync(0xffffffffu, ps1, 2);
        lsum[0] = lsum[0] * f0 + ps0;
        lsum[1] = lsum[1] * f1 + ps1;

#pragma unroll
        for (int nf = 0; nf < 16; nf++) {
            oacc[nf][0] *= f0; oacc[nf][1] *= f0;
            oacc[nf][2] *= f1; oacc[nf][3] *= f1;
        }

        uint32_t phi[2][4], plo[2][4];
#pragma unroll
        for (int kp = 0; kp < 2; kp++) {
            split2(sacc[2*kp][0],   sacc[2*kp][1],   phi[kp][0], plo[kp][0]);
            split2(sacc[2*kp][2],   sacc[2*kp][3],   phi[kp][1], plo[kp][1]);
            split2(sacc[2*kp+1][0], sacc[2*kp+1][1], phi[kp][2], plo[kp][2]);
            split2(sacc[2*kp+1][2], sacc[2*kp+1][3], phi[kp][3], plo[kp][3]);
        }

#pragma unroll
        for (int kp = 0; kp < 2; kp++) {
            uint32_t rowoff = (uint32_t)(kp * 16 * KVS) * 2;
#pragma unroll
            for (int ng = 0; ng < 8; ng++) {
                uint32_t coff = rowoff + (uint32_t)(ng * 16) * 2;
                uint32_t vh4[4], vl4[4];
                LDMATRIX_X4_T(vh4[0], vh4[1], vh4[2], vh4[3], vh_base + coff);
                LDMATRIX_X4_T(vl4[0], vl4[1], vl4[2], vl4[3], vl_base + coff);
                MMA_BF16(oacc[2*ng],   phi[kp][0], phi[kp][1], phi[kp][2], phi[kp][3], vh4[0], vh4[1]);
                MMA_BF16(oacc[2*ng+1], phi[kp][0], phi[kp][1], phi[kp][2], phi[kp][3], vh4[2], vh4[3]);
                MMA_BF16(oacc[2*ng],   plo[kp][0], plo[kp][1], plo[kp][2], plo[kp][3], vh4[0], vh4[1]);
                MMA_BF16(oacc[2*ng+1], plo[kp][0], plo[kp][1], plo[kp][2], plo[kp][3], vh4[2], vh4[3]);
                MMA_BF16(oacc[2*ng],   phi[kp][0], phi[kp][1], phi[kp][2], phi[kp][3], vl4[0], vl4[1]);
                MMA_BF16(oacc[2*ng+1], phi[kp][0], phi[kp][1], phi[kp][2], phi[kp][3], vl4[2], vl4[3]);
            }
        }
    }

    // epilogue: normalize and write pre-split bf16 Y
    float il0 = 1.0f / lsum[0];
    float il1 = 1.0f / lsum[1];
    const int row0 = qrow0 + trow;
#pragma unroll
    for (int nf = 0; nf < 16; nf++) {
        int col = h * HD + nf * 8 + tc2;
        uint32_t hh, ll;
        split2(oacc[nf][0] * il0, oacc[nf][1] * il0, hh, ll);
        *(uint32_t*)&Yh[(size_t)row0 * C_DIM + col] = hh;
        *(uint32_t*)&Yl[(size_t)row0 * C_DIM + col] = ll;
        split2(oacc[nf][2] * il1, oacc[nf][3] * il1, hh, ll);
        *(uint32_t*)&Yh[(size_t)(row0 + 8) * C_DIM + col] = hh;
        *(uint32_t*)&Yl[(size_t)(row0 + 8) * C_DIM + col] = ll;
    }
}

// ---------------------------------------------------------------------------
// Launch
// ---------------------------------------------------------------------------
extern "C" void kernel_launch(void* const* d_in, const int* in_sizes, int n_in,
                              void* d_out, int out_size)
{
    const float* x  = (const float*)d_in[0];
    const float* Wq = (const float*)d_in[1];
    const float* Wk = (const float*)d_in[2];
    const float* Wv = (const float*)d_in[3];
    const float* Wo = (const float*)d_in[4];
    float* out = (float*)d_out;

    float *Q, *Kp, *Vp;
    cudaGetSymbolAddress((void**)&Q,  g_Q);
    cudaGetSymbolAddress((void**)&Kp, g_K);
    cudaGetSymbolAddress((void**)&Vp, g_V);

    __nv_bfloat16 *xh, *xl, *yh, *yl;
    __nv_bfloat16 *wqh, *wql, *wkh, *wkl, *wvh, *wvl, *woh, *wol;
    cudaGetSymbolAddress((void**)&xh, g_xh);
    cudaGetSymbolAddress((void**)&xl, g_xl);
    cudaGetSymbolAddress((void**)&yh, g_yh);
    cudaGetSymbolAddress((void**)&yl, g_yl);
    cudaGetSymbolAddress((void**)&wqh, g_wqt_h);
    cudaGetSymbolAddress((void**)&wql, g_wqt_l);
    cudaGetSymbolAddress((void**)&wkh, g_wkt_h);
    cudaGetSymbolAddress((void**)&wkl, g_wkt_l);
    cudaGetSymbolAddress((void**)&wvh, g_wvt_h);
    cudaGetSymbolAddress((void**)&wvl, g_wvt_l);
    cudaGetSymbolAddress((void**)&woh, g_wot_h);
    cudaGetSymbolAddress((void**)&wol, g_wot_l);

    static bool attr_done = false;
    if (!attr_done) {
        cudaFuncSetAttribute(gemm_split, cudaFuncAttributeMaxDynamicSharedMemorySize, G_SMEM);
        attr_done = true;
    }

    // Prep
    rope_table_kernel<<<(T_LEN * 64 + 255) / 256, 256>>>();
    {
        int n4 = T_LEN * C_DIM / 4;
        split_f32_kernel<<<(n4 + 255) / 256, 256>>>(x, xh, xl, n4);
    }
    transpose_split_kernel<<<dim3(NKV / 32, C_DIM / 32), dim3(32, 8)>>>(Wk, wkh, wkl, C_DIM, NKV);
    transpose_split_kernel<<<dim3(NKV / 32, C_DIM / 32), dim3(32, 8)>>>(Wv, wvh, wvl, C_DIM, NKV);
    transpose_split_kernel<<<dim3(C_DIM / 32, C_DIM / 32), dim3(32, 8)>>>(Wq, wqh, wql, C_DIM, C_DIM);
    transpose_split_kernel<<<dim3(C_DIM / 32, C_DIM / 32), dim3(32, 8)>>>(Wo, woh, wol, C_DIM, C_DIM);

    // Projections
    gemm_split<<<dim3(NKV / 128, T_LEN / 128), 128, G_SMEM>>>(xh, xl, wkh, wkl, Kp, T_LEN, NKV, C_DIM);
    gemm_split<<<dim3(NKV / 128, T_LEN / 128), 128, G_SMEM>>>(xh, xl, wvh, wvl, Vp, T_LEN, NKV, C_DIM);
    gemm_split<<<dim3((HQ * HD) / 128, T_LEN / 128), 128, G_SMEM>>>(xh, xl, wqh, wql, Q, T_LEN, HQ * HD, C_DIM);

    // RoPE apply
    const int n_rope = T_LEN * HQ * 64 + T_LEN * HKV * 64;
    rope_apply_kernel<<<n_rope / 256, 256>>>(Q, Kp);

    // Attention (writes pre-split Y)
    attn_tc_kernel<<<dim3(T_LEN / 64, HQ), 128>>>(Q, Kp, Vp, yh, yl);

    // Output projection
    gemm_split<<<dim3(C_DIM / 128, T_LEN / 128), 128, G_SMEM>>>(yh, yl, woh, wol, out, T_LEN, C_DIM, C_DIM);
}